// round 2
// baseline (speedup 1.0000x reference)
#include <cuda_runtime.h>
#include <math.h>

// ---------------- static config ----------------
#define BB    8
#define HH    64
#define WWID  64
#define HWP   4096      // H*W
#define PP    32768     // B*H*W
#define DIMC  256
#define CRC   64
#define GCC   32
#define NHH   4
#define HCC   16
#define N9    9
#define OFFC  18
#define NCLS  80
#define SCALEF 0.25f    // HC^-0.5
#define MULF  5.0f

// ---------------- scratch (device globals; no allocations) ----------------
__device__ float g_xn[PP * DIMC];        // LN'd x, pixel-major [P,256]
__device__ float g_qbuf[PP * CRC];       // q [P,64]
__device__ float g_kbuf[16 * HWP * GCC]; // k channel-last [bg,h,w,32]
__device__ float g_vbuf[16 * HWP * GCC]; // v channel-last
__device__ float g_tbuf[16 * HWP * GCC]; // offset-branch intermediate [bg,hw,32]
__device__ float g_offbuf[16 * HWP * OFFC]; // sampling coords [bg,hw,18]
__device__ float g_attnout[PP * CRC];    // attention output [P,64]
__device__ float g_ybuf[PP * DIMC];      // proj+residual [P,256]

// ---------------- kernel 1: channel-LN + NCHW -> [P,C] transpose ----------------
__global__ void k_ln(const float* __restrict__ x,
                     const float* __restrict__ gam,
                     const float* __restrict__ bet)
{
    __shared__ float s[DIMC][33];
    __shared__ float red[2][8][32];
    __shared__ float smean[32], srstd[32];

    int p0 = blockIdx.x * 32;          // 32 pixels per block (never straddles batch)
    int b  = p0 >> 12;
    int hw0 = p0 & 4095;
    int tid = threadIdx.x;
    int tx = tid & 31, ty = tid >> 5;

    const float* xb = x + (size_t)b * DIMC * HWP + hw0;
    for (int c = ty; c < DIMC; c += 8)
        s[c][tx] = xb[c * HWP + tx];
    __syncthreads();

    float sum = 0.f, sq = 0.f;
    for (int c = ty; c < DIMC; c += 8) {
        float v = s[c][tx];
        sum += v; sq += v * v;
    }
    red[0][ty][tx] = sum; red[1][ty][tx] = sq;
    __syncthreads();
    if (ty == 0) {
        float s1 = 0.f, s2 = 0.f;
        #pragma unroll
        for (int j = 0; j < 8; j++) { s1 += red[0][j][tx]; s2 += red[1][j][tx]; }
        float m = s1 * (1.f / 256.f);
        float v = s2 * (1.f / 256.f) - m * m;
        smean[tx] = m;
        srstd[tx] = rsqrtf(v + 1e-5f);
    }
    __syncthreads();

    float gg = gam[tid], bb = bet[tid];
    for (int pl = 0; pl < 32; pl++) {
        g_xn[(size_t)(p0 + pl) * DIMC + tid] =
            (s[tid][pl] - smean[pl]) * srstd[pl] * gg + bb;
    }
}

// ---------------- tiled SGEMM: C[M,N] = A[M,K] * Bw[N,K]^T (+epilogue) ----------------
// MODE 0: qkv  (A=g_xn, K=256, N=192) -> scatter q/k/v
// MODE 1: proj (A=g_attnout, K=64, N=256) -> + bias + residual x -> g_ybuf (internal)
// MODE 2: cls  (A=g_ybuf, K=256, N=80) -> + bias -> strided NCHW output (d_out)
template<int MODE>
__global__ void k_gemm(const float* __restrict__ Bw,
                       const float* __restrict__ bias,
                       const float* __restrict__ resid,
                       float* __restrict__ outp)
{
    constexpr int K    = (MODE == 1) ? 64 : 256;
    constexpr int Ntot = (MODE == 0) ? 192 : (MODE == 1) ? 256 : 80;
    const float* A = (MODE == 0) ? g_xn : (MODE == 1) ? g_attnout : g_ybuf;

    const int BM = 64, BN = 64, BK = 16;
    __shared__ float As[BK][BM];
    __shared__ float Bs[BK][BN];

    int tid = threadIdx.x;          // 256 threads
    int tx = tid & 15, ty = tid >> 4;
    int row0 = blockIdx.y * BM, col0 = blockIdx.x * BN;

    float acc[4][4];
    #pragma unroll
    for (int i = 0; i < 4; i++)
        #pragma unroll
        for (int j = 0; j < 4; j++) acc[i][j] = 0.f;

    int ar  = tid >> 2;             // 0..63
    int akc = (tid & 3) * 4;        // 0,4,8,12

    for (int k0 = 0; k0 < K; k0 += BK) {
        float4 av = *(const float4*)(A + (size_t)(row0 + ar) * K + k0 + akc);
        As[akc + 0][ar] = av.x; As[akc + 1][ar] = av.y;
        As[akc + 2][ar] = av.z; As[akc + 3][ar] = av.w;

        float4 bv = make_float4(0.f, 0.f, 0.f, 0.f);
        if (col0 + ar < Ntot)
            bv = *(const float4*)(Bw + (size_t)(col0 + ar) * K + k0 + akc);
        Bs[akc + 0][ar] = bv.x; Bs[akc + 1][ar] = bv.y;
        Bs[akc + 2][ar] = bv.z; Bs[akc + 3][ar] = bv.w;
        __syncthreads();

        #pragma unroll
        for (int k = 0; k < BK; k++) {
            float4 a = *(const float4*)&As[k][ty * 4];
            float4 b = *(const float4*)&Bs[k][tx * 4];
            acc[0][0] += a.x * b.x; acc[0][1] += a.x * b.y;
            acc[0][2] += a.x * b.z; acc[0][3] += a.x * b.w;
            acc[1][0] += a.y * b.x; acc[1][1] += a.y * b.y;
            acc[1][2] += a.y * b.z; acc[1][3] += a.y * b.w;
            acc[2][0] += a.z * b.x; acc[2][1] += a.z * b.y;
            acc[2][2] += a.z * b.z; acc[2][3] += a.z * b.w;
            acc[3][0] += a.w * b.x; acc[3][1] += a.w * b.y;
            acc[3][2] += a.w * b.z; acc[3][3] += a.w * b.w;
        }
        __syncthreads();
    }

    #pragma unroll
    for (int i = 0; i < 4; i++) {
        int p = row0 + ty * 4 + i;
        int bidx = p >> 12, hw = p & 4095;
        #pragma unroll
        for (int j = 0; j < 4; j++) {
            int o = col0 + tx * 4 + j;
            float v = acc[i][j];
            if (MODE == 0) {
                if (o < 64) {
                    g_qbuf[p * 64 + o] = v;
                } else if (o < 128) {
                    int c = o - 64;
                    g_kbuf[((bidx * 2 + (c >> 5)) * HWP + hw) * GCC + (c & 31)] = v;
                } else {
                    int c = o - 128;
                    g_vbuf[((bidx * 2 + (c >> 5)) * HWP + hw) * GCC + (c & 31)] = v;
                }
            } else if (MODE == 1) {
                // write to device-global scratch directly (host cannot pass
                // a __device__ symbol address as a kernel argument)
                g_ybuf[(size_t)p * DIMC + o] =
                    v + bias[o] + resid[(size_t)bidx * DIMC * HWP + o * HWP + hw];
            } else {
                if (o < Ntot)
                    outp[(size_t)bidx * NCLS * HWP + o * HWP + hw] = v + bias[o];
            }
        }
    }
}

// ---------------- kernel 3: depthwise 3x3 + LN(32) + exact GELU ----------------
__global__ void k_dw(const float* __restrict__ wdw,
                     const float* __restrict__ g2,
                     const float* __restrict__ b2)
{
    __shared__ float sw[GCC * 9];
    __shared__ float sg[GCC], sb[GCC];
    for (int i = threadIdx.x; i < GCC * 9; i += blockDim.x) sw[i] = wdw[i];
    if (threadIdx.x < GCC) { sg[threadIdx.x] = g2[threadIdx.x]; sb[threadIdx.x] = b2[threadIdx.x]; }
    __syncthreads();

    int idx = blockIdx.x * blockDim.x + threadIdx.x;   // 0..65535
    int bg = idx >> 12, hw = idx & 4095;
    int h = hw >> 6, w = hw & 63;
    int b = bg >> 1, g = bg & 1;

    float acc[GCC];
    #pragma unroll
    for (int c = 0; c < GCC; c++) acc[c] = 0.f;

    #pragma unroll
    for (int dy = -1; dy <= 1; dy++) {
        int yy = h + dy; if (yy < 0 || yy > 63) continue;
        #pragma unroll
        for (int dx = -1; dx <= 1; dx++) {
            int xx = w + dx; if (xx < 0 || xx > 63) continue;
            const float* src = g_qbuf + (size_t)(b * HWP + yy * 64 + xx) * CRC + g * GCC;
            int kidx = (dy + 1) * 3 + (dx + 1);
            #pragma unroll
            for (int c4 = 0; c4 < GCC; c4 += 4) {
                float4 v = *(const float4*)(src + c4);
                acc[c4 + 0] += v.x * sw[(c4 + 0) * 9 + kidx];
                acc[c4 + 1] += v.y * sw[(c4 + 1) * 9 + kidx];
                acc[c4 + 2] += v.z * sw[(c4 + 2) * 9 + kidx];
                acc[c4 + 3] += v.w * sw[(c4 + 3) * 9 + kidx];
            }
        }
    }
    float m = 0.f;
    #pragma unroll
    for (int c = 0; c < GCC; c++) m += acc[c];
    m *= (1.f / GCC);
    float v = 0.f;
    #pragma unroll
    for (int c = 0; c < GCC; c++) { float d = acc[c] - m; v += d * d; }
    float rs = rsqrtf(v * (1.f / GCC) + 1e-5f);

    float* dst = g_tbuf + (size_t)idx * GCC;
    #pragma unroll
    for (int c = 0; c < GCC; c++) {
        float t = (acc[c] - m) * rs * sg[c] + sb[c];
        dst[c] = 0.5f * t * (1.f + erff(t * 0.70710678118654752f));
    }
}

// ---------------- kernel 4: 3x3 conv (32->18) + tanh*MUL + base offset ----------------
__global__ void k_off(const float* __restrict__ woff,
                      const float* __restrict__ boff,
                      const float* __restrict__ offset)
{
    __shared__ float sw[OFFC * GCC * 9];   // 5184 floats
    for (int i = threadIdx.x; i < OFFC * GCC * 9; i += blockDim.x) sw[i] = woff[i];
    __syncthreads();

    int idx = blockIdx.x * blockDim.x + threadIdx.x;
    int bg = idx >> 12, hw = idx & 4095;
    int h = hw >> 6, w = hw & 63;
    int b = bg >> 1;

    float pred[OFFC];
    #pragma unroll
    for (int o = 0; o < OFFC; o++) pred[o] = boff[o];

    for (int dy = -1; dy <= 1; dy++) {
        int yy = h + dy; if (yy < 0 || yy > 63) continue;
        for (int dx = -1; dx <= 1; dx++) {
            int xx = w + dx; if (xx < 0 || xx > 63) continue;
            const float* tp = g_tbuf + (size_t)(bg * HWP + yy * 64 + xx) * GCC;
            float tv[GCC];
            #pragma unroll
            for (int c4 = 0; c4 < GCC; c4 += 4) {
                float4 v = *(const float4*)(tp + c4);
                tv[c4] = v.x; tv[c4 + 1] = v.y; tv[c4 + 2] = v.z; tv[c4 + 3] = v.w;
            }
            int kidx = (dy + 1) * 3 + (dx + 1);
            #pragma unroll
            for (int o = 0; o < OFFC; o++) {
                float a = 0.f;
                const float* swo = sw + o * (GCC * 9) + kidx;
                #pragma unroll
                for (int c = 0; c < GCC; c++) a += tv[c] * swo[c * 9];
                pred[o] += a;
            }
        }
    }
    const float* ofs = offset + (size_t)b * OFFC * HWP + hw;
    float* dst = g_offbuf + (size_t)idx * OFFC;
    #pragma unroll
    for (int j = 0; j < OFFC; j++)
        dst[j] = tanhf(pred[j]) * MULF + ofs[j * HWP];
}

// ---------------- kernel 5: deformable gather + softmax attention ----------------
__device__ __forceinline__ void samp16(const float* __restrict__ bufh,
                                       int y, int x, float w, float s[16])
{
    if ((unsigned)x < 64u && (unsigned)y < 64u) {
        const float* q = bufh + (y * 64 + x) * GCC;
        #pragma unroll
        for (int i = 0; i < 16; i += 4) {
            float4 t = *(const float4*)(q + i);
            s[i] += w * t.x; s[i + 1] += w * t.y;
            s[i + 2] += w * t.z; s[i + 3] += w * t.w;
        }
    }
}

__global__ void k_attn(const float* __restrict__ rpb)
{
    int idx = blockIdx.x * blockDim.x + threadIdx.x;   // 0 .. P*NH-1
    int nh = idx & 3;
    int p  = idx >> 2;
    int b = p >> 12, hw = p & 4095;
    int g = nh >> 1, hb = (nh & 1) * 16;
    int bg = b * 2 + g;

    float q[16];
    const float* qp = g_qbuf + (size_t)p * CRC + nh * HCC;
    #pragma unroll
    for (int i = 0; i < 16; i++) q[i] = qp[i] * SCALEF;

    const float* off = g_offbuf + (size_t)(bg * HWP + hw) * OFFC;
    const float* kb = g_kbuf + (size_t)bg * HWP * GCC + hb;
    const float* vb = g_vbuf + (size_t)bg * HWP * GCC + hb;
    const float* rp = rpb + nh * (N9 * HCC);

    int ix[N9], iy[N9];
    float fx[N9], fy[N9], logit[N9];

    #pragma unroll
    for (int n = 0; n < N9; n++) {
        float row = off[2 * n], col = off[2 * n + 1];
        float xf = floorf(col), yf = floorf(row);
        ix[n] = (int)xf; iy[n] = (int)yf;
        fx[n] = col - xf; fy[n] = row - yf;

        float w00 = (1.f - fx[n]) * (1.f - fy[n]);
        float w10 = fx[n] * (1.f - fy[n]);
        float w01 = (1.f - fx[n]) * fy[n];
        float w11 = fx[n] * fy[n];

        float s[16];
        #pragma unroll
        for (int i = 0; i < 16; i++) s[i] = 0.f;
        samp16(kb, iy[n],     ix[n],     w00, s);
        samp16(kb, iy[n],     ix[n] + 1, w10, s);
        samp16(kb, iy[n] + 1, ix[n],     w01, s);
        samp16(kb, iy[n] + 1, ix[n] + 1, w11, s);

        float l = 0.f;
        const float* rpn = rp + n * HCC;
        #pragma unroll
        for (int i = 0; i < 16; i++) l += q[i] * (s[i] + rpn[i]);
        logit[n] = l;
    }

    float mx = logit[0];
    #pragma unroll
    for (int n = 1; n < N9; n++) mx = fmaxf(mx, logit[n]);
    float sum = 0.f;
    #pragma unroll
    for (int n = 0; n < N9; n++) { logit[n] = expf(logit[n] - mx); sum += logit[n]; }
    float inv = 1.f / sum;

    float o16[16];
    #pragma unroll
    for (int i = 0; i < 16; i++) o16[i] = 0.f;

    #pragma unroll
    for (int n = 0; n < N9; n++) {
        float wn = logit[n] * inv;
        float w00 = (1.f - fx[n]) * (1.f - fy[n]) * wn;
        float w10 = fx[n] * (1.f - fy[n]) * wn;
        float w01 = (1.f - fx[n]) * fy[n] * wn;
        float w11 = fx[n] * fy[n] * wn;
        samp16(vb, iy[n],     ix[n],     w00, o16);
        samp16(vb, iy[n],     ix[n] + 1, w10, o16);
        samp16(vb, iy[n] + 1, ix[n],     w01, o16);
        samp16(vb, iy[n] + 1, ix[n] + 1, w11, o16);
    }

    float* dst = g_attnout + (size_t)p * CRC + nh * HCC;
    #pragma unroll
    for (int i = 0; i < 16; i++) dst[i] = o16[i];
}

// ---------------- launch ----------------
extern "C" void kernel_launch(void* const* d_in, const int* in_sizes, int n_in,
                              void* d_out, int out_size)
{
    const float* x      = (const float*)d_in[0];
    const float* offset = (const float*)d_in[1];
    const float* ln1_g  = (const float*)d_in[2];
    const float* ln1_b  = (const float*)d_in[3];
    const float* w_qkv  = (const float*)d_in[4];
    const float* w_dw   = (const float*)d_in[5];
    const float* ln2_g  = (const float*)d_in[6];
    const float* ln2_b  = (const float*)d_in[7];
    const float* w_off  = (const float*)d_in[8];
    const float* b_off  = (const float*)d_in[9];
    const float* rpb    = (const float*)d_in[10];
    const float* w_proj = (const float*)d_in[11];
    const float* b_proj = (const float*)d_in[12];
    const float* w_cls  = (const float*)d_in[13];
    const float* b_cls  = (const float*)d_in[14];
    float* out = (float*)d_out;

    k_ln<<<PP / 32, 256>>>(x, ln1_g, ln1_b);
    k_gemm<0><<<dim3(3, PP / 64), 256>>>(w_qkv, nullptr, nullptr, nullptr);
    k_dw<<<(16 * HWP) / 128, 128>>>(w_dw, ln2_g, ln2_b);
    k_off<<<(16 * HWP) / 128, 128>>>(w_off, b_off, offset);
    k_attn<<<(PP * NHH) / 128, 128>>>(rpb);
    k_gemm<1><<<dim3(4, PP / 64), 256>>>(w_proj, b_proj, x, nullptr);
    k_gemm<2><<<dim3(2, PP / 64), 256>>>(w_cls, b_cls, nullptr, out);
}

// round 3
// speedup vs baseline: 1.1492x; 1.1492x over previous
#include <cuda_runtime.h>
#include <math.h>

// ---------------- static config ----------------
#define HWP   4096
#define PP    32768
#define DIMC  256
#define CRC   64
#define GCC   32
#define HCC   16
#define N9    9
#define OFFC  18
#define NCLS  80
#define SCALEF 0.25f
#define MULF  5.0f

// ---------------- scratch ----------------
__device__ float g_xn[PP * DIMC];
__device__ float g_qbuf[PP * CRC];
__device__ float g_kbuf[16 * HWP * GCC];
__device__ float g_vbuf[16 * HWP * GCC];
__device__ float g_tbuf[16 * HWP * GCC];
__device__ float g_offbuf[16 * HWP * OFFC];
__device__ float g_attnout[PP * CRC];
__device__ float g_ybuf[PP * DIMC];

// ---------------- kernel 1: channel-LN + NCHW -> [P,C] transpose ----------------
__global__ void k_ln(const float* __restrict__ x,
                     const float* __restrict__ gam,
                     const float* __restrict__ bet)
{
    __shared__ float s[DIMC][33];
    __shared__ float red[2][8][32];
    __shared__ float smean[32], srstd[32];

    int p0 = blockIdx.x * 32;
    int b  = p0 >> 12;
    int hw0 = p0 & 4095;
    int tid = threadIdx.x;
    int tx = tid & 31, ty = tid >> 5;

    const float* xb = x + (size_t)b * DIMC * HWP + hw0;
    for (int c = ty; c < DIMC; c += 8)
        s[c][tx] = xb[c * HWP + tx];
    __syncthreads();

    float sum = 0.f, sq = 0.f;
    for (int c = ty; c < DIMC; c += 8) {
        float v = s[c][tx];
        sum += v; sq += v * v;
    }
    red[0][ty][tx] = sum; red[1][ty][tx] = sq;
    __syncthreads();
    if (ty == 0) {
        float s1 = 0.f, s2 = 0.f;
        #pragma unroll
        for (int j = 0; j < 8; j++) { s1 += red[0][j][tx]; s2 += red[1][j][tx]; }
        float m = s1 * (1.f / 256.f);
        float v = s2 * (1.f / 256.f) - m * m;
        smean[tx] = m;
        srstd[tx] = rsqrtf(v + 1e-5f);
    }
    __syncthreads();

    float gg = gam[tid], bb = bet[tid];
    for (int pl = 0; pl < 32; pl++) {
        g_xn[(size_t)(p0 + pl) * DIMC + tid] =
            (s[tid][pl] - smean[pl]) * srstd[pl] * gg + bb;
    }
}

// ---------------- SGEMM 128x64 tile, 8x4 microtile ----------------
// MODE 0: qkv  (A=g_xn, K=256, N=192) -> scatter q/k/v
// MODE 1: proj (A=g_attnout, K=64, N=256) -> +bias +residual -> g_ybuf
// MODE 2: cls  (A=g_ybuf, K=256, N=80) -> +bias -> NCHW d_out
template<int MODE>
__global__ void k_gemm(const float* __restrict__ Bw,
                       const float* __restrict__ bias,
                       const float* __restrict__ resid,
                       float* __restrict__ outp)
{
    constexpr int K    = (MODE == 1) ? 64 : 256;
    constexpr int Ntot = (MODE == 0) ? 192 : (MODE == 1) ? 256 : 80;
    const float* A = (MODE == 0) ? g_xn : (MODE == 1) ? g_attnout : g_ybuf;

    const int BM = 128, BN = 64, BK = 16;
    __shared__ float As[BK][BM];
    __shared__ float Bs[BK][BN];

    int tid = threadIdx.x;               // 256 threads
    int tx = tid & 15, ty = tid >> 4;    // 16 x 16
    int row0 = blockIdx.y * BM, col0 = blockIdx.x * BN;

    float acc[8][4];
    #pragma unroll
    for (int i = 0; i < 8; i++)
        #pragma unroll
        for (int j = 0; j < 4; j++) acc[i][j] = 0.f;

    // A-load mapping: 512 float4, 2 per thread
    int a_row0 = tid >> 2;               // 0..63 (i=0), +64 (i=1)
    int a_ch   = tid & 3;                // chunk 0..3 -> k offset *4
    // B-load mapping: 256 float4, 1 per thread
    int b_row = tid >> 2;                // 0..63
    int b_ch  = tid & 3;

    for (int k0 = 0; k0 < K; k0 += BK) {
        #pragma unroll
        for (int i = 0; i < 2; i++) {
            int row = a_row0 + i * 64;
            float4 av = *(const float4*)(A + (size_t)(row0 + row) * K + k0 + a_ch * 4);
            As[a_ch * 4 + 0][row] = av.x; As[a_ch * 4 + 1][row] = av.y;
            As[a_ch * 4 + 2][row] = av.z; As[a_ch * 4 + 3][row] = av.w;
        }
        float4 bv = make_float4(0.f, 0.f, 0.f, 0.f);
        if (col0 + b_row < Ntot)
            bv = *(const float4*)(Bw + (size_t)(col0 + b_row) * K + k0 + b_ch * 4);
        Bs[b_ch * 4 + 0][b_row] = bv.x; Bs[b_ch * 4 + 1][b_row] = bv.y;
        Bs[b_ch * 4 + 2][b_row] = bv.z; Bs[b_ch * 4 + 3][b_row] = bv.w;
        __syncthreads();

        #pragma unroll
        for (int k = 0; k < BK; k++) {
            float4 a0 = *(const float4*)&As[k][ty * 8];
            float4 a1 = *(const float4*)&As[k][ty * 8 + 4];
            float4 b  = *(const float4*)&Bs[k][tx * 4];
            acc[0][0] += a0.x * b.x; acc[0][1] += a0.x * b.y; acc[0][2] += a0.x * b.z; acc[0][3] += a0.x * b.w;
            acc[1][0] += a0.y * b.x; acc[1][1] += a0.y * b.y; acc[1][2] += a0.y * b.z; acc[1][3] += a0.y * b.w;
            acc[2][0] += a0.z * b.x; acc[2][1] += a0.z * b.y; acc[2][2] += a0.z * b.z; acc[2][3] += a0.z * b.w;
            acc[3][0] += a0.w * b.x; acc[3][1] += a0.w * b.y; acc[3][2] += a0.w * b.z; acc[3][3] += a0.w * b.w;
            acc[4][0] += a1.x * b.x; acc[4][1] += a1.x * b.y; acc[4][2] += a1.x * b.z; acc[4][3] += a1.x * b.w;
            acc[5][0] += a1.y * b.x; acc[5][1] += a1.y * b.y; acc[5][2] += a1.y * b.z; acc[5][3] += a1.y * b.w;
            acc[6][0] += a1.z * b.x; acc[6][1] += a1.z * b.y; acc[6][2] += a1.z * b.z; acc[6][3] += a1.z * b.w;
            acc[7][0] += a1.w * b.x; acc[7][1] += a1.w * b.y; acc[7][2] += a1.w * b.z; acc[7][3] += a1.w * b.w;
        }
        __syncthreads();
    }

    #pragma unroll
    for (int i = 0; i < 8; i++) {
        int p = row0 + ty * 8 + i;
        int bidx = p >> 12, hw = p & 4095;
        #pragma unroll
        for (int j = 0; j < 4; j++) {
            int o = col0 + tx * 4 + j;
            float v = acc[i][j];
            if (MODE == 0) {
                if (o < 64) {
                    g_qbuf[p * 64 + o] = v;
                } else if (o < 128) {
                    int c = o - 64;
                    g_kbuf[((bidx * 2 + (c >> 5)) * HWP + hw) * GCC + (c & 31)] = v;
                } else {
                    int c = o - 128;
                    g_vbuf[((bidx * 2 + (c >> 5)) * HWP + hw) * GCC + (c & 31)] = v;
                }
            } else if (MODE == 1) {
                g_ybuf[(size_t)p * DIMC + o] =
                    v + bias[o] + resid[(size_t)bidx * DIMC * HWP + o * HWP + hw];
            } else {
                if (o < Ntot)
                    outp[(size_t)bidx * NCLS * HWP + o * HWP + hw] = v + bias[o];
            }
        }
    }
}

// ---------------- kernel 3: depthwise 3x3 + LN(32) + exact GELU ----------------
__global__ void k_dw(const float* __restrict__ wdw,
                     const float* __restrict__ g2,
                     const float* __restrict__ b2)
{
    __shared__ float sw[GCC * 9];
    __shared__ float sg[GCC], sb[GCC];
    for (int i = threadIdx.x; i < GCC * 9; i += blockDim.x) sw[i] = wdw[i];
    if (threadIdx.x < GCC) { sg[threadIdx.x] = g2[threadIdx.x]; sb[threadIdx.x] = b2[threadIdx.x]; }
    __syncthreads();

    int idx = blockIdx.x * blockDim.x + threadIdx.x;
    int bg = idx >> 12, hw = idx & 4095;
    int h = hw >> 6, w = hw & 63;
    int b = bg >> 1, g = bg & 1;

    float acc[GCC];
    #pragma unroll
    for (int c = 0; c < GCC; c++) acc[c] = 0.f;

    #pragma unroll
    for (int dy = -1; dy <= 1; dy++) {
        int yy = h + dy; if (yy < 0 || yy > 63) continue;
        #pragma unroll
        for (int dx = -1; dx <= 1; dx++) {
            int xx = w + dx; if (xx < 0 || xx > 63) continue;
            const float* src = g_qbuf + (size_t)(b * HWP + yy * 64 + xx) * CRC + g * GCC;
            int kidx = (dy + 1) * 3 + (dx + 1);
            #pragma unroll
            for (int c4 = 0; c4 < GCC; c4 += 4) {
                float4 v = *(const float4*)(src + c4);
                acc[c4 + 0] += v.x * sw[(c4 + 0) * 9 + kidx];
                acc[c4 + 1] += v.y * sw[(c4 + 1) * 9 + kidx];
                acc[c4 + 2] += v.z * sw[(c4 + 2) * 9 + kidx];
                acc[c4 + 3] += v.w * sw[(c4 + 3) * 9 + kidx];
            }
        }
    }
    float m = 0.f;
    #pragma unroll
    for (int c = 0; c < GCC; c++) m += acc[c];
    m *= (1.f / GCC);
    float v = 0.f;
    #pragma unroll
    for (int c = 0; c < GCC; c++) { float d = acc[c] - m; v += d * d; }
    float rs = rsqrtf(v * (1.f / GCC) + 1e-5f);

    float* dst = g_tbuf + (size_t)idx * GCC;
    #pragma unroll
    for (int c = 0; c < GCC; c++) {
        float t = (acc[c] - m) * rs * sg[c] + sb[c];
        dst[c] = 0.5f * t * (1.f + erff(t * 0.70710678118654752f));
    }
}

// ---------------- kernel 4: smem-tiled 3x3 conv (32->18) + tanh*MUL + base ----
// One block per (bg, output row). 128 threads: 64 cols x 2 output-groups of 9.
__global__ void k_off(const float* __restrict__ woff,
                      const float* __restrict__ boff,
                      const float* __restrict__ offset)
{
    __shared__ float4 st[8][3][66];     // c/4, row, col+1  (25344 B)
    __shared__ float  sw[9][OFFC][GCC]; // kidx, o, c       (20736 B)

    int bg = blockIdx.x >> 6;
    int h  = blockIdx.x & 63;
    int b  = bg >> 1;
    int tid = threadIdx.x;              // 128

    // weights: w_off[o][c][ky][kx] -> sw[kidx][o][c]
    for (int i = tid; i < OFFC * GCC * 9; i += 128) {
        int o = i / (GCC * 9); int rem = i - o * (GCC * 9);
        int c = rem / 9; int kidx = rem - c * 9;
        sw[kidx][o][c] = woff[i];
    }
    // zero tile (halo cols + out-of-range rows stay zero)
    float* stf = (float*)st;
    for (int i = tid; i < 8 * 3 * 66 * 4; i += 128) stf[i] = 0.f;
    __syncthreads();

    // stage rows h-1..h+1 of g_tbuf[bg] (channel-last) as float4
    for (int i = tid; i < 1536; i += 128) {
        int c4  = i & 7;
        int col = (i >> 3) & 63;
        int r   = i >> 9;
        int gr  = h - 1 + r;
        if ((unsigned)gr < 64u) {
            st[c4][r][col + 1] =
                *(const float4*)(g_tbuf + ((size_t)(bg * HWP + gr * 64 + col)) * GCC + c4 * 4);
        }
    }
    __syncthreads();

    int col = tid & 63;
    int og  = tid >> 6;                 // output group: o in [og*9, og*9+9)

    float acc[9];
    #pragma unroll
    for (int o = 0; o < 9; o++) acc[o] = boff[og * 9 + o];

    #pragma unroll
    for (int kidx = 0; kidx < 9; kidx++) {
        int ky = kidx / 3, kx = kidx % 3;
        float4 tv[8];
        #pragma unroll
        for (int c4 = 0; c4 < 8; c4++) tv[c4] = st[c4][ky][col + kx];
        #pragma unroll
        for (int o = 0; o < 9; o++) {
            const float* wp = &sw[kidx][og * 9 + o][0];
            float a = 0.f;
            #pragma unroll
            for (int c4 = 0; c4 < 8; c4++) {
                float4 w4 = *(const float4*)(wp + c4 * 4);
                a += tv[c4].x * w4.x + tv[c4].y * w4.y +
                     tv[c4].z * w4.z + tv[c4].w * w4.w;
            }
            acc[o] += a;
        }
    }

    int hw = h * 64 + col;
    const float* ofs = offset + (size_t)b * OFFC * HWP + hw;
    float* dst = g_offbuf + ((size_t)bg * HWP + hw) * OFFC + og * 9;
    #pragma unroll
    for (int o = 0; o < 9; o++)
        dst[o] = tanhf(acc[o]) * MULF + ofs[(og * 9 + o) * HWP];
}

// ---------------- kernel 5: deformable gather + softmax attention ----------------
__device__ __forceinline__ void samp16(const float* __restrict__ bufh,
                                       int y, int x, float w, float s[16])
{
    if ((unsigned)x < 64u && (unsigned)y < 64u) {
        const float* q = bufh + (y * 64 + x) * GCC;
        #pragma unroll
        for (int i = 0; i < 16; i += 4) {
            float4 t = *(const float4*)(q + i);
            s[i] += w * t.x; s[i + 1] += w * t.y;
            s[i + 2] += w * t.z; s[i + 3] += w * t.w;
        }
    }
}

__global__ void k_attn(const float* __restrict__ rpb)
{
    int idx = blockIdx.x * blockDim.x + threadIdx.x;
    int nh = idx & 3;
    int p  = idx >> 2;
    int b = p >> 12, hw = p & 4095;
    int g = nh >> 1, hb = (nh & 1) * 16;
    int bg = b * 2 + g;

    float q[16];
    const float* qp = g_qbuf + (size_t)p * CRC + nh * HCC;
    #pragma unroll
    for (int i = 0; i < 16; i++) q[i] = qp[i] * SCALEF;

    const float* off = g_offbuf + (size_t)(bg * HWP + hw) * OFFC;
    const float* kb = g_kbuf + (size_t)bg * HWP * GCC + hb;
    const float* vb = g_vbuf + (size_t)bg * HWP * GCC + hb;
    const float* rp = rpb + nh * (N9 * HCC);

    int ix[N9], iy[N9];
    float fx[N9], fy[N9], logit[N9];

    #pragma unroll
    for (int n = 0; n < N9; n++) {
        float row = off[2 * n], col = off[2 * n + 1];
        float xf = floorf(col), yf = floorf(row);
        ix[n] = (int)xf; iy[n] = (int)yf;
        fx[n] = col - xf; fy[n] = row - yf;

        float w00 = (1.f - fx[n]) * (1.f - fy[n]);
        float w10 = fx[n] * (1.f - fy[n]);
        float w01 = (1.f - fx[n]) * fy[n];
        float w11 = fx[n] * fy[n];

        float s[16];
        #pragma unroll
        for (int i = 0; i < 16; i++) s[i] = 0.f;
        samp16(kb, iy[n],     ix[n],     w00, s);
        samp16(kb, iy[n],     ix[n] + 1, w10, s);
        samp16(kb, iy[n] + 1, ix[n],     w01, s);
        samp16(kb, iy[n] + 1, ix[n] + 1, w11, s);

        float l = 0.f;
        const float* rpn = rp + n * HCC;
        #pragma unroll
        for (int i = 0; i < 16; i++) l += q[i] * (s[i] + rpn[i]);
        logit[n] = l;
    }

    float mx = logit[0];
    #pragma unroll
    for (int n = 1; n < N9; n++) mx = fmaxf(mx, logit[n]);
    float sum = 0.f;
    #pragma unroll
    for (int n = 0; n < N9; n++) { logit[n] = expf(logit[n] - mx); sum += logit[n]; }
    float inv = 1.f / sum;

    float o16[16];
    #pragma unroll
    for (int i = 0; i < 16; i++) o16[i] = 0.f;

    #pragma unroll
    for (int n = 0; n < N9; n++) {
        float wn = logit[n] * inv;
        float w00 = (1.f - fx[n]) * (1.f - fy[n]) * wn;
        float w10 = fx[n] * (1.f - fy[n]) * wn;
        float w01 = (1.f - fx[n]) * fy[n] * wn;
        float w11 = fx[n] * fy[n] * wn;
        samp16(vb, iy[n],     ix[n],     w00, o16);
        samp16(vb, iy[n],     ix[n] + 1, w10, o16);
        samp16(vb, iy[n] + 1, ix[n],     w01, o16);
        samp16(vb, iy[n] + 1, ix[n] + 1, w11, o16);
    }

    float* dst = g_attnout + (size_t)p * CRC + nh * HCC;
    #pragma unroll
    for (int i = 0; i < 16; i++) dst[i] = o16[i];
}

// ---------------- launch ----------------
extern "C" void kernel_launch(void* const* d_in, const int* in_sizes, int n_in,
                              void* d_out, int out_size)
{
    const float* x      = (const float*)d_in[0];
    const float* offset = (const float*)d_in[1];
    const float* ln1_g  = (const float*)d_in[2];
    const float* ln1_b  = (const float*)d_in[3];
    const float* w_qkv  = (const float*)d_in[4];
    const float* w_dw   = (const float*)d_in[5];
    const float* ln2_g  = (const float*)d_in[6];
    const float* ln2_b  = (const float*)d_in[7];
    const float* w_off  = (const float*)d_in[8];
    const float* b_off  = (const float*)d_in[9];
    const float* rpb    = (const float*)d_in[10];
    const float* w_proj = (const float*)d_in[11];
    const float* b_proj = (const float*)d_in[12];
    const float* w_cls  = (const float*)d_in[13];
    const float* b_cls  = (const float*)d_in[14];
    float* out = (float*)d_out;

    k_ln<<<PP / 32, 256>>>(x, ln1_g, ln1_b);
    k_gemm<0><<<dim3(3, PP / 128), 256>>>(w_qkv, nullptr, nullptr, nullptr);
    k_dw<<<(16 * HWP) / 128, 128>>>(w_dw, ln2_g, ln2_b);
    k_off<<<16 * 64, 128>>>(w_off, b_off, offset);
    k_attn<<<(PP * 4) / 128, 128>>>(rpb);
    k_gemm<1><<<dim3(4, PP / 128), 256>>>(w_proj, b_proj, x, nullptr);
    k_gemm<2><<<dim3(2, PP / 128), 256>>>(w_cls, b_cls, nullptr, out);
}

// round 4
// speedup vs baseline: 1.1826x; 1.0291x over previous
#include <cuda_runtime.h>
#include <math.h>

// ---------------- static config ----------------
#define HWP   4096
#define PP    32768
#define DIMC  256
#define CRC   64
#define GCC   32
#define HCC   16
#define N9    9
#define OFFC  18
#define NCLS  80
#define SCALEF 0.25f
#define MULF  5.0f

// ---------------- scratch ----------------
__device__ float g_xn[PP * DIMC];
__device__ float g_qbuf[PP * CRC];
__device__ float g_kbuf[16 * HWP * GCC];
__device__ float g_vbuf[16 * HWP * GCC];
__device__ float g_tbuf[16 * HWP * GCC];
__device__ float g_offbuf[16 * HWP * OFFC];
__device__ float g_attnout[PP * CRC];
__device__ float g_ybuf[PP * DIMC];

// ---------------- kernel 1: channel-LN + NCHW -> [P,C] transpose ----------------
__global__ void k_ln(const float* __restrict__ x,
                     const float* __restrict__ gam,
                     const float* __restrict__ bet)
{
    __shared__ float s[DIMC][33];
    __shared__ float red[2][8][32];
    __shared__ float smean[32], srstd[32];

    int p0 = blockIdx.x * 32;
    int b  = p0 >> 12;
    int hw0 = p0 & 4095;
    int tid = threadIdx.x;
    int tx = tid & 31, ty = tid >> 5;

    const float* xb = x + (size_t)b * DIMC * HWP + hw0;
    for (int c = ty; c < DIMC; c += 8)
        s[c][tx] = xb[c * HWP + tx];
    __syncthreads();

    float sum = 0.f, sq = 0.f;
    for (int c = ty; c < DIMC; c += 8) {
        float v = s[c][tx];
        sum += v; sq += v * v;
    }
    red[0][ty][tx] = sum; red[1][ty][tx] = sq;
    __syncthreads();
    if (ty == 0) {
        float s1 = 0.f, s2 = 0.f;
        #pragma unroll
        for (int j = 0; j < 8; j++) { s1 += red[0][j][tx]; s2 += red[1][j][tx]; }
        float m = s1 * (1.f / 256.f);
        float v = s2 * (1.f / 256.f) - m * m;
        smean[tx] = m;
        srstd[tx] = rsqrtf(v + 1e-5f);
    }
    __syncthreads();

    float gg = gam[tid], bb = bet[tid];
    for (int pl = 0; pl < 32; pl++) {
        g_xn[(size_t)(p0 + pl) * DIMC + tid] =
            (s[tid][pl] - smean[pl]) * srstd[pl] * gg + bb;
    }
}

// ---------------- SGEMM 128x64 tile, 8x4 microtile ----------------
template<int MODE>
__global__ void k_gemm(const float* __restrict__ Bw,
                       const float* __restrict__ bias,
                       const float* __restrict__ resid,
                       float* __restrict__ outp)
{
    constexpr int K    = (MODE == 1) ? 64 : 256;
    constexpr int Ntot = (MODE == 0) ? 192 : (MODE == 1) ? 256 : 80;
    const float* A = (MODE == 0) ? g_xn : (MODE == 1) ? g_attnout : g_ybuf;

    const int BM = 128, BN = 64, BK = 16;
    __shared__ float As[BK][BM];
    __shared__ float Bs[BK][BN];

    int tid = threadIdx.x;
    int tx = tid & 15, ty = tid >> 4;
    int row0 = blockIdx.y * BM, col0 = blockIdx.x * BN;

    float acc[8][4];
    #pragma unroll
    for (int i = 0; i < 8; i++)
        #pragma unroll
        for (int j = 0; j < 4; j++) acc[i][j] = 0.f;

    int a_row0 = tid >> 2;
    int a_ch   = tid & 3;
    int b_row = tid >> 2;
    int b_ch  = tid & 3;

    for (int k0 = 0; k0 < K; k0 += BK) {
        #pragma unroll
        for (int i = 0; i < 2; i++) {
            int row = a_row0 + i * 64;
            float4 av = *(const float4*)(A + (size_t)(row0 + row) * K + k0 + a_ch * 4);
            As[a_ch * 4 + 0][row] = av.x; As[a_ch * 4 + 1][row] = av.y;
            As[a_ch * 4 + 2][row] = av.z; As[a_ch * 4 + 3][row] = av.w;
        }
        float4 bv = make_float4(0.f, 0.f, 0.f, 0.f);
        if (col0 + b_row < Ntot)
            bv = *(const float4*)(Bw + (size_t)(col0 + b_row) * K + k0 + b_ch * 4);
        Bs[b_ch * 4 + 0][b_row] = bv.x; Bs[b_ch * 4 + 1][b_row] = bv.y;
        Bs[b_ch * 4 + 2][b_row] = bv.z; Bs[b_ch * 4 + 3][b_row] = bv.w;
        __syncthreads();

        #pragma unroll
        for (int k = 0; k < BK; k++) {
            float4 a0 = *(const float4*)&As[k][ty * 8];
            float4 a1 = *(const float4*)&As[k][ty * 8 + 4];
            float4 b  = *(const float4*)&Bs[k][tx * 4];
            acc[0][0] += a0.x * b.x; acc[0][1] += a0.x * b.y; acc[0][2] += a0.x * b.z; acc[0][3] += a0.x * b.w;
            acc[1][0] += a0.y * b.x; acc[1][1] += a0.y * b.y; acc[1][2] += a0.y * b.z; acc[1][3] += a0.y * b.w;
            acc[2][0] += a0.z * b.x; acc[2][1] += a0.z * b.y; acc[2][2] += a0.z * b.z; acc[2][3] += a0.z * b.w;
            acc[3][0] += a0.w * b.x; acc[3][1] += a0.w * b.y; acc[3][2] += a0.w * b.z; acc[3][3] += a0.w * b.w;
            acc[4][0] += a1.x * b.x; acc[4][1] += a1.x * b.y; acc[4][2] += a1.x * b.z; acc[4][3] += a1.x * b.w;
            acc[5][0] += a1.y * b.x; acc[5][1] += a1.y * b.y; acc[5][2] += a1.y * b.z; acc[5][3] += a1.y * b.w;
            acc[6][0] += a1.z * b.x; acc[6][1] += a1.z * b.y; acc[6][2] += a1.z * b.z; acc[6][3] += a1.z * b.w;
            acc[7][0] += a1.w * b.x; acc[7][1] += a1.w * b.y; acc[7][2] += a1.w * b.z; acc[7][3] += a1.w * b.w;
        }
        __syncthreads();
    }

    #pragma unroll
    for (int i = 0; i < 8; i++) {
        int p = row0 + ty * 8 + i;
        int bidx = p >> 12, hw = p & 4095;
        #pragma unroll
        for (int j = 0; j < 4; j++) {
            int o = col0 + tx * 4 + j;
            float v = acc[i][j];
            if (MODE == 0) {
                if (o < 64) {
                    g_qbuf[p * 64 + o] = v;
                } else if (o < 128) {
                    int c = o - 64;
                    g_kbuf[((bidx * 2 + (c >> 5)) * HWP + hw) * GCC + (c & 31)] = v;
                } else {
                    int c = o - 128;
                    g_vbuf[((bidx * 2 + (c >> 5)) * HWP + hw) * GCC + (c & 31)] = v;
                }
            } else if (MODE == 1) {
                g_ybuf[(size_t)p * DIMC + o] =
                    v + bias[o] + resid[(size_t)bidx * DIMC * HWP + o * HWP + hw];
            } else {
                if (o < Ntot)
                    outp[(size_t)bidx * NCLS * HWP + o * HWP + hw] = v + bias[o];
            }
        }
    }
}

// ---------------- kernel 3: smem-tiled depthwise 3x3 + LN(32) + GELU ----------
// Block = (bg, 4 output rows). 256 threads = 64 cols x 4 rows.
// Dynamic smem tile: [8 c4][6 rows][66 cols] float4 of q-group channels.
__global__ void __launch_bounds__(256, 2) k_dw(const float* __restrict__ wdw,
                                               const float* __restrict__ g2,
                                               const float* __restrict__ b2)
{
    extern __shared__ float4 st4[];     // 8*6*66 = 3168 float4
    __shared__ float sw[GCC * 9];
    __shared__ float sg[GCC], sb[GCC];

    int bg = blockIdx.x >> 4;
    int h0 = (blockIdx.x & 15) * 4;
    int b = bg >> 1, g = bg & 1;
    int tid = threadIdx.x;

    for (int i = tid; i < GCC * 9; i += 256) sw[i] = wdw[i];
    if (tid < GCC) { sg[tid] = g2[tid]; sb[tid] = b2[tid]; }
    for (int i = tid; i < 3168; i += 256) st4[i] = make_float4(0.f, 0.f, 0.f, 0.f);
    __syncthreads();

    // stage rows h0-1 .. h0+4 of q-group slice (coalesced)
    for (int i = tid; i < 3072; i += 256) {
        int c4 = i & 7, col = (i >> 3) & 63, r = i >> 9;
        int gr = h0 - 1 + r;
        if ((unsigned)gr < 64u)
            st4[(c4 * 6 + r) * 66 + col + 1] =
                *(const float4*)(g_qbuf + ((size_t)(b * HWP + gr * 64 + col)) * CRC + g * GCC + c4 * 4);
    }
    __syncthreads();

    int col = tid & 63;
    int row = tid >> 6;
    int h = h0 + row;

    float acc[GCC];
    #pragma unroll
    for (int c = 0; c < GCC; c++) acc[c] = 0.f;

    #pragma unroll
    for (int ky = 0; ky < 3; ky++) {
        #pragma unroll
        for (int kx = 0; kx < 3; kx++) {
            int kidx = ky * 3 + kx;
            #pragma unroll
            for (int c4 = 0; c4 < 8; c4++) {
                float4 v = st4[(c4 * 6 + row + ky) * 66 + col + kx];
                acc[c4 * 4 + 0] += v.x * sw[(c4 * 4 + 0) * 9 + kidx];
                acc[c4 * 4 + 1] += v.y * sw[(c4 * 4 + 1) * 9 + kidx];
                acc[c4 * 4 + 2] += v.z * sw[(c4 * 4 + 2) * 9 + kidx];
                acc[c4 * 4 + 3] += v.w * sw[(c4 * 4 + 3) * 9 + kidx];
            }
        }
    }

    float m = 0.f;
    #pragma unroll
    for (int c = 0; c < GCC; c++) m += acc[c];
    m *= (1.f / GCC);
    float v = 0.f;
    #pragma unroll
    for (int c = 0; c < GCC; c++) { float d = acc[c] - m; v += d * d; }
    float rs = rsqrtf(v * (1.f / GCC) + 1e-5f);

    float* dst = g_tbuf + ((size_t)bg * HWP + h * 64 + col) * GCC;
    #pragma unroll
    for (int c = 0; c < GCC; c++) {
        float t = (acc[c] - m) * rs * sg[c] + sb[c];
        dst[c] = 0.5f * t * (1.f + erff(t * 0.70710678118654752f));
    }
}

// ---------------- kernel 4: smem-tiled 3x3 conv (32->18) + tanh*MUL + base ----
// Block = (bg, 4 rows). 256 threads = 32 pxg x 2 og x 4 rows; each thread
// computes 2 pixels (cols pxg and pxg+32) x 9 outputs.
__global__ void __launch_bounds__(256, 2) k_off(const float* __restrict__ woff,
                                                const float* __restrict__ boff,
                                                const float* __restrict__ offset)
{
    extern __shared__ float4 dyn4[];
    float4* st4 = dyn4;                           // 8*6*66 = 3168 float4
    float*  sw  = (float*)(dyn4 + 3168);          // [9][18][32]
    float4* sw4 = (float4*)sw;                    // [kidx][o][c4]

    int bg = blockIdx.x >> 4;
    int h0 = (blockIdx.x & 15) * 4;
    int tid = threadIdx.x;

    // weights: w_off[o][c][ky][kx] -> sw[kidx][o][c]
    for (int i = tid; i < OFFC * GCC * 9; i += 256) {
        int o = i / (GCC * 9); int rem = i - o * (GCC * 9);
        int c = rem / 9; int kidx = rem - c * 9;
        sw[(kidx * OFFC + o) * GCC + c] = woff[i];
    }
    for (int i = tid; i < 3168; i += 256) st4[i] = make_float4(0.f, 0.f, 0.f, 0.f);
    __syncthreads();

    for (int i = tid; i < 3072; i += 256) {
        int c4 = i & 7, col = (i >> 3) & 63, r = i >> 9;
        int gr = h0 - 1 + r;
        if ((unsigned)gr < 64u)
            st4[(c4 * 6 + r) * 66 + col + 1] =
                *(const float4*)(g_tbuf + ((size_t)(bg * HWP + gr * 64 + col)) * GCC + c4 * 4);
    }
    __syncthreads();

    int pxg = tid & 31;
    int og  = (tid >> 5) & 1;
    int row = tid >> 6;
    int h = h0 + row;
    int b = bg >> 1;

    float acc[2][9];
    #pragma unroll
    for (int o = 0; o < 9; o++) {
        float bz = boff[og * 9 + o];
        acc[0][o] = bz; acc[1][o] = bz;
    }

    #pragma unroll
    for (int c4 = 0; c4 < 8; c4++) {
        #pragma unroll
        for (int ky = 0; ky < 3; ky++) {
            const float4* trow = &st4[(c4 * 6 + row + ky) * 66];
            float4 t0[3], t1[3];
            #pragma unroll
            for (int kx = 0; kx < 3; kx++) {
                t0[kx] = trow[pxg + kx];
                t1[kx] = trow[pxg + 32 + kx];
            }
            #pragma unroll
            for (int kx = 0; kx < 3; kx++) {
                int kidx = ky * 3 + kx;
                #pragma unroll
                for (int o = 0; o < 9; o++) {
                    float4 w = sw4[(kidx * OFFC + og * 9 + o) * 8 + c4];
                    acc[0][o] += t0[kx].x * w.x + t0[kx].y * w.y +
                                 t0[kx].z * w.z + t0[kx].w * w.w;
                    acc[1][o] += t1[kx].x * w.x + t1[kx].y * w.y +
                                 t1[kx].z * w.z + t1[kx].w * w.w;
                }
            }
        }
    }

    #pragma unroll
    for (int p = 0; p < 2; p++) {
        int hw = h * 64 + pxg + p * 32;
        const float* ofs = offset + (size_t)b * OFFC * HWP + hw;
        float* dst = g_offbuf + ((size_t)bg * HWP + hw) * OFFC + og * 9;
        #pragma unroll
        for (int o = 0; o < 9; o++)
            dst[o] = tanhf(acc[p][o]) * MULF + ofs[(og * 9 + o) * HWP];
    }
}

// ---------------- kernel 5: deformable gather + softmax attention ----------------
__device__ __forceinline__ void samp16(const float* __restrict__ bufh,
                                       int y, int x, float w, float s[16])
{
    if ((unsigned)x < 64u && (unsigned)y < 64u) {
        const float* q = bufh + (y * 64 + x) * GCC;
        #pragma unroll
        for (int i = 0; i < 16; i += 4) {
            float4 t = *(const float4*)(q + i);
            s[i] += w * t.x; s[i + 1] += w * t.y;
            s[i + 2] += w * t.z; s[i + 3] += w * t.w;
        }
    }
}

__global__ void k_attn(const float* __restrict__ rpb)
{
    int idx = blockIdx.x * blockDim.x + threadIdx.x;
    int nh = idx & 3;
    int p  = idx >> 2;
    int b = p >> 12, hw = p & 4095;
    int g = nh >> 1, hb = (nh & 1) * 16;
    int bg = b * 2 + g;

    float q[16];
    const float* qp = g_qbuf + (size_t)p * CRC + nh * HCC;
    #pragma unroll
    for (int i = 0; i < 16; i++) q[i] = qp[i] * SCALEF;

    const float* off = g_offbuf + (size_t)(bg * HWP + hw) * OFFC;
    const float* kb = g_kbuf + (size_t)bg * HWP * GCC + hb;
    const float* vb = g_vbuf + (size_t)bg * HWP * GCC + hb;
    const float* rp = rpb + nh * (N9 * HCC);

    int ix[N9], iy[N9];
    float fx[N9], fy[N9], logit[N9];

    #pragma unroll
    for (int n = 0; n < N9; n++) {
        float row = off[2 * n], col = off[2 * n + 1];
        float xf = floorf(col), yf = floorf(row);
        ix[n] = (int)xf; iy[n] = (int)yf;
        fx[n] = col - xf; fy[n] = row - yf;

        float w00 = (1.f - fx[n]) * (1.f - fy[n]);
        float w10 = fx[n] * (1.f - fy[n]);
        float w01 = (1.f - fx[n]) * fy[n];
        float w11 = fx[n] * fy[n];

        float s[16];
        #pragma unroll
        for (int i = 0; i < 16; i++) s[i] = 0.f;
        samp16(kb, iy[n],     ix[n],     w00, s);
        samp16(kb, iy[n],     ix[n] + 1, w10, s);
        samp16(kb, iy[n] + 1, ix[n],     w01, s);
        samp16(kb, iy[n] + 1, ix[n] + 1, w11, s);

        float l = 0.f;
        const float* rpn = rp + n * HCC;
        #pragma unroll
        for (int i = 0; i < 16; i++) l += q[i] * (s[i] + rpn[i]);
        logit[n] = l;
    }

    float mx = logit[0];
    #pragma unroll
    for (int n = 1; n < N9; n++) mx = fmaxf(mx, logit[n]);
    float sum = 0.f;
    #pragma unroll
    for (int n = 0; n < N9; n++) { logit[n] = expf(logit[n] - mx); sum += logit[n]; }
    float inv = 1.f / sum;

    float o16[16];
    #pragma unroll
    for (int i = 0; i < 16; i++) o16[i] = 0.f;

    #pragma unroll
    for (int n = 0; n < N9; n++) {
        float wn = logit[n] * inv;
        float w00 = (1.f - fx[n]) * (1.f - fy[n]) * wn;
        float w10 = fx[n] * (1.f - fy[n]) * wn;
        float w01 = (1.f - fx[n]) * fy[n] * wn;
        float w11 = fx[n] * fy[n] * wn;
        samp16(vb, iy[n],     ix[n],     w00, o16);
        samp16(vb, iy[n],     ix[n] + 1, w10, o16);
        samp16(vb, iy[n] + 1, ix[n],     w01, o16);
        samp16(vb, iy[n] + 1, ix[n] + 1, w11, o16);
    }

    float* dst = g_attnout + (size_t)p * CRC + nh * HCC;
    #pragma unroll
    for (int i = 0; i < 16; i++) dst[i] = o16[i];
}

// ---------------- launch ----------------
extern "C" void kernel_launch(void* const* d_in, const int* in_sizes, int n_in,
                              void* d_out, int out_size)
{
    const float* x      = (const float*)d_in[0];
    const float* offset = (const float*)d_in[1];
    const float* ln1_g  = (const float*)d_in[2];
    const float* ln1_b  = (const float*)d_in[3];
    const float* w_qkv  = (const float*)d_in[4];
    const float* w_dw   = (const float*)d_in[5];
    const float* ln2_g  = (const float*)d_in[6];
    const float* ln2_b  = (const float*)d_in[7];
    const float* w_off  = (const float*)d_in[8];
    const float* b_off  = (const float*)d_in[9];
    const float* rpb    = (const float*)d_in[10];
    const float* w_proj = (const float*)d_in[11];
    const float* b_proj = (const float*)d_in[12];
    const float* w_cls  = (const float*)d_in[13];
    const float* b_cls  = (const float*)d_in[14];
    float* out = (float*)d_out;

    const int dwSmem  = 3168 * 16;           // 50688 B
    const int offSmem = 3168 * 16 + 5184 * 4; // 71424 B
    static int configured = 0;
    if (!configured) {
        cudaFuncSetAttribute(k_dw,  cudaFuncAttributeMaxDynamicSharedMemorySize, dwSmem);
        cudaFuncSetAttribute(k_off, cudaFuncAttributeMaxDynamicSharedMemorySize, offSmem);
        configured = 1;
    }

    k_ln<<<PP / 32, 256>>>(x, ln1_g, ln1_b);
    k_gemm<0><<<dim3(3, PP / 128), 256>>>(w_qkv, nullptr, nullptr, nullptr);
    k_dw<<<16 * 16, 256, dwSmem>>>(w_dw, ln2_g, ln2_b);
    k_off<<<16 * 16, 256, offSmem>>>(w_off, b_off, offset);
    k_attn<<<(PP * 4) / 128, 128>>>(rpb);
    k_gemm<1><<<dim3(4, PP / 128), 256>>>(w_proj, b_proj, x, nullptr);
    k_gemm<2><<<dim3(2, PP / 128), 256>>>(w_cls, b_cls, nullptr, out);
}

// round 5
// speedup vs baseline: 1.5414x; 1.3034x over previous
#include <cuda_runtime.h>
#include <cuda_bf16.h>
#include <math.h>

// ---------------- static config ----------------
#define HWP   4096
#define PP    32768
#define DIMC  256
#define CRC   64
#define GCC   32
#define HCC   16
#define N9    9
#define OFFC  18
#define NCLS  80
#define SCALEF 0.25f
#define MULF  5.0f

// ---------------- scratch ----------------
__device__ float g_xn[PP * DIMC];
__device__ float g_qbuf[PP * CRC];
__device__ float g_kbuf[16 * HWP * GCC];
__device__ float g_vbuf[16 * HWP * GCC];
__device__ float g_tbuf[16 * HWP * GCC];
__device__ float g_offbuf[16 * HWP * OFFC];
__device__ float g_attnout[PP * CRC];
__device__ float g_ybuf[PP * DIMC];

// ---------------- kernel 1: channel-LN + NCHW -> [P,C] transpose ----------------
__global__ void k_ln(const float* __restrict__ x,
                     const float* __restrict__ gam,
                     const float* __restrict__ bet)
{
    __shared__ float s[DIMC][33];
    __shared__ float red[2][8][32];
    __shared__ float smean[32], srstd[32];

    int p0 = blockIdx.x * 32;
    int b  = p0 >> 12;
    int hw0 = p0 & 4095;
    int tid = threadIdx.x;
    int tx = tid & 31, ty = tid >> 5;

    const float* xb = x + (size_t)b * DIMC * HWP + hw0;
    for (int c = ty; c < DIMC; c += 8)
        s[c][tx] = xb[c * HWP + tx];
    __syncthreads();

    float sum = 0.f, sq = 0.f;
    for (int c = ty; c < DIMC; c += 8) {
        float v = s[c][tx];
        sum += v; sq += v * v;
    }
    red[0][ty][tx] = sum; red[1][ty][tx] = sq;
    __syncthreads();
    if (ty == 0) {
        float s1 = 0.f, s2 = 0.f;
        #pragma unroll
        for (int j = 0; j < 8; j++) { s1 += red[0][j][tx]; s2 += red[1][j][tx]; }
        float m = s1 * (1.f / 256.f);
        float v = s2 * (1.f / 256.f) - m * m;
        smean[tx] = m;
        srstd[tx] = rsqrtf(v + 1e-5f);
    }
    __syncthreads();

    float gg = gam[tid], bb = bet[tid];
    for (int pl = 0; pl < 32; pl++) {
        g_xn[(size_t)(p0 + pl) * DIMC + tid] =
            (s[tid][pl] - smean[pl]) * srstd[pl] * gg + bb;
    }
}

// ---------------- helpers: bf16 split + mma ----------------
__device__ __forceinline__ void cvt_pair(float x0, float x1,
                                         unsigned& hi, unsigned& lo)
{
    __nv_bfloat16 h0 = __float2bfloat16(x0);
    __nv_bfloat16 h1 = __float2bfloat16(x1);
    float r0 = x0 - __bfloat162float(h0);
    float r1 = x1 - __bfloat162float(h1);
    __nv_bfloat16 l0 = __float2bfloat16(r0);
    __nv_bfloat16 l1 = __float2bfloat16(r1);
    unsigned short u0 = *(unsigned short*)&h0, u1 = *(unsigned short*)&h1;
    unsigned short v0 = *(unsigned short*)&l0, v1 = *(unsigned short*)&l1;
    hi = (unsigned)u0 | ((unsigned)u1 << 16);
    lo = (unsigned)v0 | ((unsigned)v1 << 16);
}

__device__ __forceinline__ void mma_bf16(float* c,
                                         unsigned a0, unsigned a1, unsigned a2, unsigned a3,
                                         unsigned b0, unsigned b1)
{
    asm volatile(
        "mma.sync.aligned.m16n8k16.row.col.f32.bf16.bf16.f32 "
        "{%0,%1,%2,%3}, {%4,%5,%6,%7}, {%8,%9}, {%0,%1,%2,%3};\n"
        : "+f"(c[0]), "+f"(c[1]), "+f"(c[2]), "+f"(c[3])
        : "r"(a0), "r"(a1), "r"(a2), "r"(a3), "r"(b0), "r"(b1));
}

// ---------------- tensor-core GEMM (bf16 split, 3xMMA == fp32-accurate) -------
// C[M,N] = A[M,K] * Bw[N,K]^T, block tile 128x64, 8 warps of 32x32.
// MODE 0: qkv  (A=g_xn, K=256, N=192) -> scatter q/k/v
// MODE 1: proj (A=g_attnout, K=64, N=256) -> +bias +residual -> g_ybuf
// MODE 2: cls  (A=g_ybuf, K=256, N=80) -> +bias -> NCHW d_out
template<int MODE>
__global__ void __launch_bounds__(256) k_gemm(const float* __restrict__ Bw,
                                              const float* __restrict__ bias,
                                              const float* __restrict__ resid,
                                              float* __restrict__ outp)
{
    constexpr int K    = (MODE == 1) ? 64 : 256;
    constexpr int Ntot = (MODE == 0) ? 192 : (MODE == 1) ? 256 : 80;
    const float* A = (MODE == 0) ? g_xn : (MODE == 1) ? g_attnout : g_ybuf;

    // smem: packed bf16x2, kpair-major stride 20 (conflict-free: 20*r mod 32
    // spans all banks over 8 consecutive rows)
    __shared__ unsigned Ah[128][20], Al[128][20];
    __shared__ unsigned Bh[64][20],  Bl[64][20];

    int tid = threadIdx.x;
    int lane = tid & 31;
    int warpId = tid >> 5;
    int warpM = warpId & 3;           // 4 warps over M
    int warpN = warpId >> 2;          // 2 warps over N
    int row0 = blockIdx.y * 128, col0 = blockIdx.x * 64;

    float acc[2][4][4];
    #pragma unroll
    for (int mt = 0; mt < 2; mt++)
        #pragma unroll
        for (int nt = 0; nt < 4; nt++)
            #pragma unroll
            for (int e = 0; e < 4; e++) acc[mt][nt][e] = 0.f;

    for (int k0 = 0; k0 < K; k0 += 32) {
        __syncthreads();
        // stage A: 128 rows x 32 k = 1024 float4-chunks... (1024 float4? no:
        // 128*32/4 = 1024 float4), 4 per thread
        #pragma unroll
        for (int i = 0; i < 4; i++) {
            int id = tid + i * 256;           // 0..1023
            int row = id >> 3, f = id & 7;    // f: which float4 in the 32-k row
            float4 v = *(const float4*)(A + (size_t)(row0 + row) * K + k0 + f * 4);
            unsigned h0, l0, h1, l1;
            cvt_pair(v.x, v.y, h0, l0);
            cvt_pair(v.z, v.w, h1, l1);
            Ah[row][f * 2] = h0; Ah[row][f * 2 + 1] = h1;
            Al[row][f * 2] = l0; Al[row][f * 2 + 1] = l1;
        }
        // stage B: 64 rows x 32 k = 512 float4, 2 per thread
        #pragma unroll
        for (int i = 0; i < 2; i++) {
            int id = tid + i * 256;           // 0..511
            int row = id >> 3, f = id & 7;
            float4 v = make_float4(0.f, 0.f, 0.f, 0.f);
            if (col0 + row < Ntot)
                v = *(const float4*)(Bw + (size_t)(col0 + row) * K + k0 + f * 4);
            unsigned h0, l0, h1, l1;
            cvt_pair(v.x, v.y, h0, l0);
            cvt_pair(v.z, v.w, h1, l1);
            Bh[row][f * 2] = h0; Bh[row][f * 2 + 1] = h1;
            Bl[row][f * 2] = l0; Bl[row][f * 2 + 1] = l1;
        }
        __syncthreads();

        #pragma unroll
        for (int kk = 0; kk < 2; kk++) {      // two k16 steps per stage
            int kb = kk * 8 + (lane & 3);
            unsigned ah[2][4], al[2][4];
            #pragma unroll
            for (int mt = 0; mt < 2; mt++) {
                int ar = warpM * 32 + mt * 16 + (lane >> 2);
                ah[mt][0] = Ah[ar][kb];     ah[mt][1] = Ah[ar + 8][kb];
                ah[mt][2] = Ah[ar][kb + 4]; ah[mt][3] = Ah[ar + 8][kb + 4];
                al[mt][0] = Al[ar][kb];     al[mt][1] = Al[ar + 8][kb];
                al[mt][2] = Al[ar][kb + 4]; al[mt][3] = Al[ar + 8][kb + 4];
            }
            #pragma unroll
            for (int nt = 0; nt < 4; nt++) {
                int br = warpN * 32 + nt * 8 + (lane >> 2);
                unsigned bh0 = Bh[br][kb], bh1 = Bh[br][kb + 4];
                unsigned bl0 = Bl[br][kb], bl1 = Bl[br][kb + 4];
                #pragma unroll
                for (int mt = 0; mt < 2; mt++) {
                    mma_bf16(acc[mt][nt], ah[mt][0], ah[mt][1], ah[mt][2], ah[mt][3], bh0, bh1);
                    mma_bf16(acc[mt][nt], ah[mt][0], ah[mt][1], ah[mt][2], ah[mt][3], bl0, bl1);
                    mma_bf16(acc[mt][nt], al[mt][0], al[mt][1], al[mt][2], al[mt][3], bh0, bh1);
                }
            }
        }
    }

    // epilogue
    #pragma unroll
    for (int mt = 0; mt < 2; mt++) {
        #pragma unroll
        for (int nt = 0; nt < 4; nt++) {
            #pragma unroll
            for (int e = 0; e < 4; e++) {
                int p = row0 + warpM * 32 + mt * 16 + (lane >> 2) + ((e >= 2) ? 8 : 0);
                int o = col0 + warpN * 32 + nt * 8 + 2 * (lane & 3) + (e & 1);
                float v = acc[mt][nt][e];
                int bidx = p >> 12, hw = p & 4095;
                if (MODE == 0) {
                    if (o < 64) {
                        g_qbuf[p * 64 + o] = v;
                    } else if (o < 128) {
                        int c = o - 64;
                        g_kbuf[((bidx * 2 + (c >> 5)) * HWP + hw) * GCC + (c & 31)] = v;
                    } else {
                        int c = o - 128;
                        g_vbuf[((bidx * 2 + (c >> 5)) * HWP + hw) * GCC + (c & 31)] = v;
                    }
                } else if (MODE == 1) {
                    g_ybuf[(size_t)p * DIMC + o] =
                        v + bias[o] + resid[(size_t)bidx * DIMC * HWP + o * HWP + hw];
                } else {
                    if (o < Ntot)
                        outp[(size_t)bidx * NCLS * HWP + o * HWP + hw] = v + bias[o];
                }
            }
        }
    }
}

// ---------------- kernel 3: smem-tiled depthwise 3x3 + LN(32) + GELU ----------
__global__ void __launch_bounds__(256, 2) k_dw(const float* __restrict__ wdw,
                                               const float* __restrict__ g2,
                                               const float* __restrict__ b2)
{
    extern __shared__ float4 st4[];
    __shared__ float sw[GCC * 9];
    __shared__ float sg[GCC], sb[GCC];

    int bg = blockIdx.x >> 4;
    int h0 = (blockIdx.x & 15) * 4;
    int b = bg >> 1, g = bg & 1;
    int tid = threadIdx.x;

    for (int i = tid; i < GCC * 9; i += 256) sw[i] = wdw[i];
    if (tid < GCC) { sg[tid] = g2[tid]; sb[tid] = b2[tid]; }
    for (int i = tid; i < 3168; i += 256) st4[i] = make_float4(0.f, 0.f, 0.f, 0.f);
    __syncthreads();

    for (int i = tid; i < 3072; i += 256) {
        int c4 = i & 7, col = (i >> 3) & 63, r = i >> 9;
        int gr = h0 - 1 + r;
        if ((unsigned)gr < 64u)
            st4[(c4 * 6 + r) * 66 + col + 1] =
                *(const float4*)(g_qbuf + ((size_t)(b * HWP + gr * 64 + col)) * CRC + g * GCC + c4 * 4);
    }
    __syncthreads();

    int col = tid & 63;
    int row = tid >> 6;
    int h = h0 + row;

    float acc[GCC];
    #pragma unroll
    for (int c = 0; c < GCC; c++) acc[c] = 0.f;

    #pragma unroll
    for (int ky = 0; ky < 3; ky++) {
        #pragma unroll
        for (int kx = 0; kx < 3; kx++) {
            int kidx = ky * 3 + kx;
            #pragma unroll
            for (int c4 = 0; c4 < 8; c4++) {
                float4 v = st4[(c4 * 6 + row + ky) * 66 + col + kx];
                acc[c4 * 4 + 0] += v.x * sw[(c4 * 4 + 0) * 9 + kidx];
                acc[c4 * 4 + 1] += v.y * sw[(c4 * 4 + 1) * 9 + kidx];
                acc[c4 * 4 + 2] += v.z * sw[(c4 * 4 + 2) * 9 + kidx];
                acc[c4 * 4 + 3] += v.w * sw[(c4 * 4 + 3) * 9 + kidx];
            }
        }
    }

    float m = 0.f;
    #pragma unroll
    for (int c = 0; c < GCC; c++) m += acc[c];
    m *= (1.f / GCC);
    float v = 0.f;
    #pragma unroll
    for (int c = 0; c < GCC; c++) { float d = acc[c] - m; v += d * d; }
    float rs = rsqrtf(v * (1.f / GCC) + 1e-5f);

    float* dst = g_tbuf + ((size_t)bg * HWP + h * 64 + col) * GCC;
    #pragma unroll
    for (int c = 0; c < GCC; c++) {
        float t = (acc[c] - m) * rs * sg[c] + sb[c];
        dst[c] = 0.5f * t * (1.f + erff(t * 0.70710678118654752f));
    }
}

// ---------------- kernel 4: smem-tiled 3x3 conv (32->18) + tanh*MUL + base ----
__global__ void __launch_bounds__(256, 2) k_off(const float* __restrict__ woff,
                                                const float* __restrict__ boff,
                                                const float* __restrict__ offset)
{
    extern __shared__ float4 dyn4[];
    float4* st4 = dyn4;
    float*  sw  = (float*)(dyn4 + 3168);
    float4* sw4 = (float4*)sw;

    int bg = blockIdx.x >> 4;
    int h0 = (blockIdx.x & 15) * 4;
    int tid = threadIdx.x;

    for (int i = tid; i < OFFC * GCC * 9; i += 256) {
        int o = i / (GCC * 9); int rem = i - o * (GCC * 9);
        int c = rem / 9; int kidx = rem - c * 9;
        sw[(kidx * OFFC + o) * GCC + c] = woff[i];
    }
    for (int i = tid; i < 3168; i += 256) st4[i] = make_float4(0.f, 0.f, 0.f, 0.f);
    __syncthreads();

    for (int i = tid; i < 3072; i += 256) {
        int c4 = i & 7, col = (i >> 3) & 63, r = i >> 9;
        int gr = h0 - 1 + r;
        if ((unsigned)gr < 64u)
            st4[(c4 * 6 + r) * 66 + col + 1] =
                *(const float4*)(g_tbuf + ((size_t)(bg * HWP + gr * 64 + col)) * GCC + c4 * 4);
    }
    __syncthreads();

    int pxg = tid & 31;
    int og  = (tid >> 5) & 1;
    int row = tid >> 6;
    int h = h0 + row;
    int b = bg >> 1;

    float acc[2][9];
    #pragma unroll
    for (int o = 0; o < 9; o++) {
        float bz = boff[og * 9 + o];
        acc[0][o] = bz; acc[1][o] = bz;
    }

    #pragma unroll
    for (int c4 = 0; c4 < 8; c4++) {
        #pragma unroll
        for (int ky = 0; ky < 3; ky++) {
            const float4* trow = &st4[(c4 * 6 + row + ky) * 66];
            float4 t0[3], t1[3];
            #pragma unroll
            for (int kx = 0; kx < 3; kx++) {
                t0[kx] = trow[pxg + kx];
                t1[kx] = trow[pxg + 32 + kx];
            }
            #pragma unroll
            for (int kx = 0; kx < 3; kx++) {
                int kidx = ky * 3 + kx;
                #pragma unroll
                for (int o = 0; o < 9; o++) {
                    float4 w = sw4[(kidx * OFFC + og * 9 + o) * 8 + c4];
                    acc[0][o] += t0[kx].x * w.x + t0[kx].y * w.y +
                                 t0[kx].z * w.z + t0[kx].w * w.w;
                    acc[1][o] += t1[kx].x * w.x + t1[kx].y * w.y +
                                 t1[kx].z * w.z + t1[kx].w * w.w;
                }
            }
        }
    }

    #pragma unroll
    for (int p = 0; p < 2; p++) {
        int hw = h * 64 + pxg + p * 32;
        const float* ofs = offset + (size_t)b * OFFC * HWP + hw;
        float* dst = g_offbuf + ((size_t)bg * HWP + hw) * OFFC + og * 9;
        #pragma unroll
        for (int o = 0; o < 9; o++)
            dst[o] = tanhf(acc[p][o]) * MULF + ofs[(og * 9 + o) * HWP];
    }
}

// ---------------- kernel 5: deformable gather + softmax attention ----------------
__device__ __forceinline__ void samp16(const float* __restrict__ bufh,
                                       int y, int x, float w, float s[16])
{
    if ((unsigned)x < 64u && (unsigned)y < 64u) {
        const float* q = bufh + (y * 64 + x) * GCC;
        #pragma unroll
        for (int i = 0; i < 16; i += 4) {
            float4 t = *(const float4*)(q + i);
            s[i] += w * t.x; s[i + 1] += w * t.y;
            s[i + 2] += w * t.z; s[i + 3] += w * t.w;
        }
    }
}

__global__ void k_attn(const float* __restrict__ rpb)
{
    int idx = blockIdx.x * blockDim.x + threadIdx.x;
    int nh = idx & 3;
    int p  = idx >> 2;
    int b = p >> 12, hw = p & 4095;
    int g = nh >> 1, hb = (nh & 1) * 16;
    int bg = b * 2 + g;

    float q[16];
    const float* qp = g_qbuf + (size_t)p * CRC + nh * HCC;
    #pragma unroll
    for (int i = 0; i < 16; i++) q[i] = qp[i] * SCALEF;

    const float* off = g_offbuf + (size_t)(bg * HWP + hw) * OFFC;
    const float* kb = g_kbuf + (size_t)bg * HWP * GCC + hb;
    const float* vb = g_vbuf + (size_t)bg * HWP * GCC + hb;
    const float* rp = rpb + nh * (N9 * HCC);

    int ix[N9], iy[N9];
    float fx[N9], fy[N9], logit[N9];

    #pragma unroll
    for (int n = 0; n < N9; n++) {
        float row = off[2 * n], col = off[2 * n + 1];
        float xf = floorf(col), yf = floorf(row);
        ix[n] = (int)xf; iy[n] = (int)yf;
        fx[n] = col - xf; fy[n] = row - yf;

        float w00 = (1.f - fx[n]) * (1.f - fy[n]);
        float w10 = fx[n] * (1.f - fy[n]);
        float w01 = (1.f - fx[n]) * fy[n];
        float w11 = fx[n] * fy[n];

        float s[16];
        #pragma unroll
        for (int i = 0; i < 16; i++) s[i] = 0.f;
        samp16(kb, iy[n],     ix[n],     w00, s);
        samp16(kb, iy[n],     ix[n] + 1, w10, s);
        samp16(kb, iy[n] + 1, ix[n],     w01, s);
        samp16(kb, iy[n] + 1, ix[n] + 1, w11, s);

        float l = 0.f;
        const float* rpn = rp + n * HCC;
        #pragma unroll
        for (int i = 0; i < 16; i++) l += q[i] * (s[i] + rpn[i]);
        logit[n] = l;
    }

    float mx = logit[0];
    #pragma unroll
    for (int n = 1; n < N9; n++) mx = fmaxf(mx, logit[n]);
    float sum = 0.f;
    #pragma unroll
    for (int n = 0; n < N9; n++) { logit[n] = expf(logit[n] - mx); sum += logit[n]; }
    float inv = 1.f / sum;

    float o16[16];
    #pragma unroll
    for (int i = 0; i < 16; i++) o16[i] = 0.f;

    #pragma unroll
    for (int n = 0; n < N9; n++) {
        float wn = logit[n] * inv;
        float w00 = (1.f - fx[n]) * (1.f - fy[n]) * wn;
        float w10 = fx[n] * (1.f - fy[n]) * wn;
        float w01 = (1.f - fx[n]) * fy[n] * wn;
        float w11 = fx[n] * fy[n] * wn;
        samp16(vb, iy[n],     ix[n],     w00, o16);
        samp16(vb, iy[n],     ix[n] + 1, w10, o16);
        samp16(vb, iy[n] + 1, ix[n],     w01, o16);
        samp16(vb, iy[n] + 1, ix[n] + 1, w11, o16);
    }

    float* dst = g_attnout + (size_t)p * CRC + nh * HCC;
    #pragma unroll
    for (int i = 0; i < 16; i++) dst[i] = o16[i];
}

// ---------------- launch ----------------
extern "C" void kernel_launch(void* const* d_in, const int* in_sizes, int n_in,
                              void* d_out, int out_size)
{
    const float* x      = (const float*)d_in[0];
    const float* offset = (const float*)d_in[1];
    const float* ln1_g  = (const float*)d_in[2];
    const float* ln1_b  = (const float*)d_in[3];
    const float* w_qkv  = (const float*)d_in[4];
    const float* w_dw   = (const float*)d_in[5];
    const float* ln2_g  = (const float*)d_in[6];
    const float* ln2_b  = (const float*)d_in[7];
    const float* w_off  = (const float*)d_in[8];
    const float* b_off  = (const float*)d_in[9];
    const float* rpb    = (const float*)d_in[10];
    const float* w_proj = (const float*)d_in[11];
    const float* b_proj = (const float*)d_in[12];
    const float* w_cls  = (const float*)d_in[13];
    const float* b_cls  = (const float*)d_in[14];
    float* out = (float*)d_out;

    const int dwSmem  = 3168 * 16;
    const int offSmem = 3168 * 16 + 5184 * 4;
    static int configured = 0;
    if (!configured) {
        cudaFuncSetAttribute(k_dw,  cudaFuncAttributeMaxDynamicSharedMemorySize, dwSmem);
        cudaFuncSetAttribute(k_off, cudaFuncAttributeMaxDynamicSharedMemorySize, offSmem);
        configured = 1;
    }

    k_ln<<<PP / 32, 256>>>(x, ln1_g, ln1_b);
    k_gemm<0><<<dim3(3, PP / 128), 256>>>(w_qkv, nullptr, nullptr, nullptr);
    k_dw<<<16 * 16, 256, dwSmem>>>(w_dw, ln2_g, ln2_b);
    k_off<<<16 * 16, 256, offSmem>>>(w_off, b_off, offset);
    k_attn<<<(PP * 4) / 128, 128>>>(rpb);
    k_gemm<1><<<dim3(4, PP / 128), 256>>>(w_proj, b_proj, x, nullptr);
    k_gemm<2><<<dim3(2, PP / 128), 256>>>(w_cls, b_cls, nullptr, out);
}

// round 6
// speedup vs baseline: 1.6667x; 1.0813x over previous
#include <cuda_runtime.h>
#include <cuda_bf16.h>
#include <cuda_fp16.h>
#include <math.h>

// ---------------- static config ----------------
#define HWP   4096
#define PP    32768
#define DIMC  256
#define CRC   64
#define GCC   32
#define HCC   16
#define N9    9
#define OFFC  18
#define NCLS  80
#define SCALEF 0.25f
#define MULF  5.0f

// ---------------- scratch ----------------
__device__ float  g_xn[PP * DIMC];
__device__ float  g_qbuf[PP * CRC];
__device__ __half g_kbufh[16 * HWP * GCC];   // k fp16, channel-last [bg,h,w,32]
__device__ __half g_vbufh[16 * HWP * GCC];   // v fp16
__device__ float  g_tbuf[16 * HWP * GCC];
__device__ float  g_offbuf[16 * HWP * OFFC];
__device__ float  g_attnout[PP * CRC];
__device__ float  g_ybuf[PP * DIMC];

// ---------------- kernel 1: channel-LN + NCHW -> [P,C] transpose ----------------
__global__ void k_ln(const float* __restrict__ x,
                     const float* __restrict__ gam,
                     const float* __restrict__ bet)
{
    __shared__ float s[DIMC][33];
    __shared__ float red[2][8][32];
    __shared__ float smean[32], srstd[32];

    int p0 = blockIdx.x * 32;
    int b  = p0 >> 12;
    int hw0 = p0 & 4095;
    int tid = threadIdx.x;
    int tx = tid & 31, ty = tid >> 5;

    const float* xb = x + (size_t)b * DIMC * HWP + hw0;
    for (int c = ty; c < DIMC; c += 8)
        s[c][tx] = xb[c * HWP + tx];
    __syncthreads();

    float sum = 0.f, sq = 0.f;
    for (int c = ty; c < DIMC; c += 8) {
        float v = s[c][tx];
        sum += v; sq += v * v;
    }
    red[0][ty][tx] = sum; red[1][ty][tx] = sq;
    __syncthreads();
    if (ty == 0) {
        float s1 = 0.f, s2 = 0.f;
        #pragma unroll
        for (int j = 0; j < 8; j++) { s1 += red[0][j][tx]; s2 += red[1][j][tx]; }
        float m = s1 * (1.f / 256.f);
        float v = s2 * (1.f / 256.f) - m * m;
        smean[tx] = m;
        srstd[tx] = rsqrtf(v + 1e-5f);
    }
    __syncthreads();

    float gg = gam[tid], bb = bet[tid];
    for (int pl = 0; pl < 32; pl++) {
        g_xn[(size_t)(p0 + pl) * DIMC + tid] =
            (s[tid][pl] - smean[pl]) * srstd[pl] * gg + bb;
    }
}

// ---------------- helpers: bf16 split + mma ----------------
__device__ __forceinline__ void cvt_pair(float x0, float x1,
                                         unsigned& hi, unsigned& lo)
{
    __nv_bfloat16 h0 = __float2bfloat16(x0);
    __nv_bfloat16 h1 = __float2bfloat16(x1);
    float r0 = x0 - __bfloat162float(h0);
    float r1 = x1 - __bfloat162float(h1);
    __nv_bfloat16 l0 = __float2bfloat16(r0);
    __nv_bfloat16 l1 = __float2bfloat16(r1);
    unsigned short u0 = *(unsigned short*)&h0, u1 = *(unsigned short*)&h1;
    unsigned short v0 = *(unsigned short*)&l0, v1 = *(unsigned short*)&l1;
    hi = (unsigned)u0 | ((unsigned)u1 << 16);
    lo = (unsigned)v0 | ((unsigned)v1 << 16);
}

__device__ __forceinline__ void mma_bf16(float* c,
                                         unsigned a0, unsigned a1, unsigned a2, unsigned a3,
                                         unsigned b0, unsigned b1)
{
    asm volatile(
        "mma.sync.aligned.m16n8k16.row.col.f32.bf16.bf16.f32 "
        "{%0,%1,%2,%3}, {%4,%5,%6,%7}, {%8,%9}, {%0,%1,%2,%3};\n"
        : "+f"(c[0]), "+f"(c[1]), "+f"(c[2]), "+f"(c[3])
        : "r"(a0), "r"(a1), "r"(a2), "r"(a3), "r"(b0), "r"(b1));
}

// ---------------- tensor-core GEMM (bf16 split, 3xMMA) -------
template<int MODE>
__global__ void __launch_bounds__(256) k_gemm(const float* __restrict__ Bw,
                                              const float* __restrict__ bias,
                                              const float* __restrict__ resid,
                                              float* __restrict__ outp)
{
    constexpr int K    = (MODE == 1) ? 64 : 256;
    constexpr int Ntot = (MODE == 0) ? 192 : (MODE == 1) ? 256 : 80;
    const float* A = (MODE == 0) ? g_xn : (MODE == 1) ? g_attnout : g_ybuf;

    __shared__ unsigned Ah[128][20], Al[128][20];
    __shared__ unsigned Bh[64][20],  Bl[64][20];

    int tid = threadIdx.x;
    int lane = tid & 31;
    int warpId = tid >> 5;
    int warpM = warpId & 3;
    int warpN = warpId >> 2;
    int row0 = blockIdx.y * 128, col0 = blockIdx.x * 64;

    float acc[2][4][4];
    #pragma unroll
    for (int mt = 0; mt < 2; mt++)
        #pragma unroll
        for (int nt = 0; nt < 4; nt++)
            #pragma unroll
            for (int e = 0; e < 4; e++) acc[mt][nt][e] = 0.f;

    for (int k0 = 0; k0 < K; k0 += 32) {
        __syncthreads();
        #pragma unroll
        for (int i = 0; i < 4; i++) {
            int id = tid + i * 256;
            int row = id >> 3, f = id & 7;
            float4 v = *(const float4*)(A + (size_t)(row0 + row) * K + k0 + f * 4);
            unsigned h0, l0, h1, l1;
            cvt_pair(v.x, v.y, h0, l0);
            cvt_pair(v.z, v.w, h1, l1);
            Ah[row][f * 2] = h0; Ah[row][f * 2 + 1] = h1;
            Al[row][f * 2] = l0; Al[row][f * 2 + 1] = l1;
        }
        #pragma unroll
        for (int i = 0; i < 2; i++) {
            int id = tid + i * 256;
            int row = id >> 3, f = id & 7;
            float4 v = make_float4(0.f, 0.f, 0.f, 0.f);
            if (col0 + row < Ntot)
                v = *(const float4*)(Bw + (size_t)(col0 + row) * K + k0 + f * 4);
            unsigned h0, l0, h1, l1;
            cvt_pair(v.x, v.y, h0, l0);
            cvt_pair(v.z, v.w, h1, l1);
            Bh[row][f * 2] = h0; Bh[row][f * 2 + 1] = h1;
            Bl[row][f * 2] = l0; Bl[row][f * 2 + 1] = l1;
        }
        __syncthreads();

        #pragma unroll
        for (int kk = 0; kk < 2; kk++) {
            int kb = kk * 8 + (lane & 3);
            unsigned ah[2][4], al[2][4];
            #pragma unroll
            for (int mt = 0; mt < 2; mt++) {
                int ar = warpM * 32 + mt * 16 + (lane >> 2);
                ah[mt][0] = Ah[ar][kb];     ah[mt][1] = Ah[ar + 8][kb];
                ah[mt][2] = Ah[ar][kb + 4]; ah[mt][3] = Ah[ar + 8][kb + 4];
                al[mt][0] = Al[ar][kb];     al[mt][1] = Al[ar + 8][kb];
                al[mt][2] = Al[ar][kb + 4]; al[mt][3] = Al[ar + 8][kb + 4];
            }
            #pragma unroll
            for (int nt = 0; nt < 4; nt++) {
                int br = warpN * 32 + nt * 8 + (lane >> 2);
                unsigned bh0 = Bh[br][kb], bh1 = Bh[br][kb + 4];
                unsigned bl0 = Bl[br][kb], bl1 = Bl[br][kb + 4];
                #pragma unroll
                for (int mt = 0; mt < 2; mt++) {
                    mma_bf16(acc[mt][nt], ah[mt][0], ah[mt][1], ah[mt][2], ah[mt][3], bh0, bh1);
                    mma_bf16(acc[mt][nt], ah[mt][0], ah[mt][1], ah[mt][2], ah[mt][3], bl0, bl1);
                    mma_bf16(acc[mt][nt], al[mt][0], al[mt][1], al[mt][2], al[mt][3], bh0, bh1);
                }
            }
        }
    }

    #pragma unroll
    for (int mt = 0; mt < 2; mt++) {
        #pragma unroll
        for (int nt = 0; nt < 4; nt++) {
            #pragma unroll
            for (int e = 0; e < 4; e++) {
                int p = row0 + warpM * 32 + mt * 16 + (lane >> 2) + ((e >= 2) ? 8 : 0);
                int o = col0 + warpN * 32 + nt * 8 + 2 * (lane & 3) + (e & 1);
                float v = acc[mt][nt][e];
                int bidx = p >> 12, hw = p & 4095;
                if (MODE == 0) {
                    if (o < 64) {
                        g_qbuf[p * 64 + o] = v;
                    } else if (o < 128) {
                        int c = o - 64;
                        g_kbufh[((size_t)(bidx * 2 + (c >> 5)) * HWP + hw) * GCC + (c & 31)] =
                            __float2half(v);
                    } else {
                        int c = o - 128;
                        g_vbufh[((size_t)(bidx * 2 + (c >> 5)) * HWP + hw) * GCC + (c & 31)] =
                            __float2half(v);
                    }
                } else if (MODE == 1) {
                    g_ybuf[(size_t)p * DIMC + o] =
                        v + bias[o] + resid[(size_t)bidx * DIMC * HWP + o * HWP + hw];
                } else {
                    if (o < Ntot)
                        outp[(size_t)bidx * NCLS * HWP + o * HWP + hw] = v + bias[o];
                }
            }
        }
    }
}

// ---------------- kernel 3: smem-tiled depthwise 3x3 + LN(32) + GELU ----------
__global__ void __launch_bounds__(256, 2) k_dw(const float* __restrict__ wdw,
                                               const float* __restrict__ g2,
                                               const float* __restrict__ b2)
{
    extern __shared__ float4 st4[];
    __shared__ float sw[GCC * 9];
    __shared__ float sg[GCC], sb[GCC];

    int bg = blockIdx.x >> 4;
    int h0 = (blockIdx.x & 15) * 4;
    int b = bg >> 1, g = bg & 1;
    int tid = threadIdx.x;

    for (int i = tid; i < GCC * 9; i += 256) sw[i] = wdw[i];
    if (tid < GCC) { sg[tid] = g2[tid]; sb[tid] = b2[tid]; }
    for (int i = tid; i < 3168; i += 256) st4[i] = make_float4(0.f, 0.f, 0.f, 0.f);
    __syncthreads();

    for (int i = tid; i < 3072; i += 256) {
        int c4 = i & 7, col = (i >> 3) & 63, r = i >> 9;
        int gr = h0 - 1 + r;
        if ((unsigned)gr < 64u)
            st4[(c4 * 6 + r) * 66 + col + 1] =
                *(const float4*)(g_qbuf + ((size_t)(b * HWP + gr * 64 + col)) * CRC + g * GCC + c4 * 4);
    }
    __syncthreads();

    int col = tid & 63;
    int row = tid >> 6;
    int h = h0 + row;

    float acc[GCC];
    #pragma unroll
    for (int c = 0; c < GCC; c++) acc[c] = 0.f;

    #pragma unroll
    for (int ky = 0; ky < 3; ky++) {
        #pragma unroll
        for (int kx = 0; kx < 3; kx++) {
            int kidx = ky * 3 + kx;
            #pragma unroll
            for (int c4 = 0; c4 < 8; c4++) {
                float4 v = st4[(c4 * 6 + row + ky) * 66 + col + kx];
                acc[c4 * 4 + 0] += v.x * sw[(c4 * 4 + 0) * 9 + kidx];
                acc[c4 * 4 + 1] += v.y * sw[(c4 * 4 + 1) * 9 + kidx];
                acc[c4 * 4 + 2] += v.z * sw[(c4 * 4 + 2) * 9 + kidx];
                acc[c4 * 4 + 3] += v.w * sw[(c4 * 4 + 3) * 9 + kidx];
            }
        }
    }

    float m = 0.f;
    #pragma unroll
    for (int c = 0; c < GCC; c++) m += acc[c];
    m *= (1.f / GCC);
    float v = 0.f;
    #pragma unroll
    for (int c = 0; c < GCC; c++) { float d = acc[c] - m; v += d * d; }
    float rs = rsqrtf(v * (1.f / GCC) + 1e-5f);

    float* dst = g_tbuf + ((size_t)bg * HWP + h * 64 + col) * GCC;
    #pragma unroll
    for (int c = 0; c < GCC; c++) {
        float t = (acc[c] - m) * rs * sg[c] + sb[c];
        dst[c] = 0.5f * t * (1.f + erff(t * 0.70710678118654752f));
    }
}

// ---------------- kernel 4: smem-tiled 3x3 conv (32->18) + tanh*MUL + base ----
__global__ void __launch_bounds__(256, 2) k_off(const float* __restrict__ woff,
                                                const float* __restrict__ boff,
                                                const float* __restrict__ offset)
{
    extern __shared__ float4 dyn4[];
    float4* st4 = dyn4;
    float*  sw  = (float*)(dyn4 + 3168);
    float4* sw4 = (float4*)sw;

    int bg = blockIdx.x >> 4;
    int h0 = (blockIdx.x & 15) * 4;
    int tid = threadIdx.x;

    for (int i = tid; i < OFFC * GCC * 9; i += 256) {
        int o = i / (GCC * 9); int rem = i - o * (GCC * 9);
        int c = rem / 9; int kidx = rem - c * 9;
        sw[(kidx * OFFC + o) * GCC + c] = woff[i];
    }
    for (int i = tid; i < 3168; i += 256) st4[i] = make_float4(0.f, 0.f, 0.f, 0.f);
    __syncthreads();

    for (int i = tid; i < 3072; i += 256) {
        int c4 = i & 7, col = (i >> 3) & 63, r = i >> 9;
        int gr = h0 - 1 + r;
        if ((unsigned)gr < 64u)
            st4[(c4 * 6 + r) * 66 + col + 1] =
                *(const float4*)(g_tbuf + ((size_t)(bg * HWP + gr * 64 + col)) * GCC + c4 * 4);
    }
    __syncthreads();

    int pxg = tid & 31;
    int og  = (tid >> 5) & 1;
    int row = tid >> 6;
    int h = h0 + row;
    int b = bg >> 1;

    float acc[2][9];
    #pragma unroll
    for (int o = 0; o < 9; o++) {
        float bz = boff[og * 9 + o];
        acc[0][o] = bz; acc[1][o] = bz;
    }

    #pragma unroll
    for (int c4 = 0; c4 < 8; c4++) {
        #pragma unroll
        for (int ky = 0; ky < 3; ky++) {
            const float4* trow = &st4[(c4 * 6 + row + ky) * 66];
            float4 t0[3], t1[3];
            #pragma unroll
            for (int kx = 0; kx < 3; kx++) {
                t0[kx] = trow[pxg + kx];
                t1[kx] = trow[pxg + 32 + kx];
            }
            #pragma unroll
            for (int kx = 0; kx < 3; kx++) {
                int kidx = ky * 3 + kx;
                #pragma unroll
                for (int o = 0; o < 9; o++) {
                    float4 w = sw4[(kidx * OFFC + og * 9 + o) * 8 + c4];
                    acc[0][o] += t0[kx].x * w.x + t0[kx].y * w.y +
                                 t0[kx].z * w.z + t0[kx].w * w.w;
                    acc[1][o] += t1[kx].x * w.x + t1[kx].y * w.y +
                                 t1[kx].z * w.z + t1[kx].w * w.w;
                }
            }
        }
    }

    #pragma unroll
    for (int p = 0; p < 2; p++) {
        int hw = h * 64 + pxg + p * 32;
        const float* ofs = offset + (size_t)b * OFFC * HWP + hw;
        float* dst = g_offbuf + ((size_t)bg * HWP + hw) * OFFC + og * 9;
        #pragma unroll
        for (int o = 0; o < 9; o++)
            dst[o] = tanhf(acc[p][o]) * MULF + ofs[(og * 9 + o) * HWP];
    }
}

// ---------------- kernel 5: deformable gather + softmax attention (fp16 k/v) ---
__device__ __forceinline__ void samp16h(const __half* __restrict__ bufh,
                                        int y, int x, float w, float s[16])
{
    if ((unsigned)x < 64u && (unsigned)y < 64u) {
        const uint4* q = (const uint4*)(bufh + (y * 64 + x) * GCC);
        uint4 u0 = q[0], u1 = q[1];
        const __half2* h0 = (const __half2*)&u0;
        const __half2* h1 = (const __half2*)&u1;
        #pragma unroll
        for (int i = 0; i < 4; i++) {
            float2 f = __half22float2(h0[i]);
            s[2 * i]     += w * f.x;
            s[2 * i + 1] += w * f.y;
        }
        #pragma unroll
        for (int i = 0; i < 4; i++) {
            float2 f = __half22float2(h1[i]);
            s[8 + 2 * i]     += w * f.x;
            s[8 + 2 * i + 1] += w * f.y;
        }
    }
}

__global__ void k_attn(const float* __restrict__ rpb)
{
    int idx = blockIdx.x * blockDim.x + threadIdx.x;
    int nh = idx & 3;
    int p  = idx >> 2;
    int b = p >> 12, hw = p & 4095;
    int g = nh >> 1, hb = (nh & 1) * 16;
    int bg = b * 2 + g;

    float q[16];
    const float* qp = g_qbuf + (size_t)p * CRC + nh * HCC;
    #pragma unroll
    for (int i = 0; i < 16; i++) q[i] = qp[i] * SCALEF;

    const float* off = g_offbuf + (size_t)(bg * HWP + hw) * OFFC;
    const __half* kb = g_kbufh + (size_t)bg * HWP * GCC + hb;
    const __half* vb = g_vbufh + (size_t)bg * HWP * GCC + hb;
    const float* rp = rpb + nh * (N9 * HCC);

    int ix[N9], iy[N9];
    float fx[N9], fy[N9], logit[N9];

    #pragma unroll
    for (int n = 0; n < N9; n++) {
        float row = off[2 * n], col = off[2 * n + 1];
        float xf = floorf(col), yf = floorf(row);
        ix[n] = (int)xf; iy[n] = (int)yf;
        fx[n] = col - xf; fy[n] = row - yf;

        float w00 = (1.f - fx[n]) * (1.f - fy[n]);
        float w10 = fx[n] * (1.f - fy[n]);
        float w01 = (1.f - fx[n]) * fy[n];
        float w11 = fx[n] * fy[n];

        float s[16];
        #pragma unroll
        for (int i = 0; i < 16; i++) s[i] = 0.f;
        samp16h(kb, iy[n],     ix[n],     w00, s);
        samp16h(kb, iy[n],     ix[n] + 1, w10, s);
        samp16h(kb, iy[n] + 1, ix[n],     w01, s);
        samp16h(kb, iy[n] + 1, ix[n] + 1, w11, s);

        float l = 0.f;
        const float* rpn = rp + n * HCC;
        #pragma unroll
        for (int i = 0; i < 16; i++) l += q[i] * (s[i] + rpn[i]);
        logit[n] = l;
    }

    float mx = logit[0];
    #pragma unroll
    for (int n = 1; n < N9; n++) mx = fmaxf(mx, logit[n]);
    float sum = 0.f;
    #pragma unroll
    for (int n = 0; n < N9; n++) { logit[n] = expf(logit[n] - mx); sum += logit[n]; }
    float inv = 1.f / sum;

    float o16[16];
    #pragma unroll
    for (int i = 0; i < 16; i++) o16[i] = 0.f;

    #pragma unroll
    for (int n = 0; n < N9; n++) {
        float wn = logit[n] * inv;
        float w00 = (1.f - fx[n]) * (1.f - fy[n]) * wn;
        float w10 = fx[n] * (1.f - fy[n]) * wn;
        float w01 = (1.f - fx[n]) * fy[n] * wn;
        float w11 = fx[n] * fy[n] * wn;
        samp16h(vb, iy[n],     ix[n],     w00, o16);
        samp16h(vb, iy[n],     ix[n] + 1, w10, o16);
        samp16h(vb, iy[n] + 1, ix[n],     w01, o16);
        samp16h(vb, iy[n] + 1, ix[n] + 1, w11, o16);
    }

    float* dst = g_attnout + (size_t)p * CRC + nh * HCC;
    #pragma unroll
    for (int i = 0; i < 16; i++) dst[i] = o16[i];
}

// ---------------- launch ----------------
extern "C" void kernel_launch(void* const* d_in, const int* in_sizes, int n_in,
                              void* d_out, int out_size)
{
    const float* x      = (const float*)d_in[0];
    const float* offset = (const float*)d_in[1];
    const float* ln1_g  = (const float*)d_in[2];
    const float* ln1_b  = (const float*)d_in[3];
    const float* w_qkv  = (const float*)d_in[4];
    const float* w_dw   = (const float*)d_in[5];
    const float* ln2_g  = (const float*)d_in[6];
    const float* ln2_b  = (const float*)d_in[7];
    const float* w_off  = (const float*)d_in[8];
    const float* b_off  = (const float*)d_in[9];
    const float* rpb    = (const float*)d_in[10];
    const float* w_proj = (const float*)d_in[11];
    const float* b_proj = (const float*)d_in[12];
    const float* w_cls  = (const float*)d_in[13];
    const float* b_cls  = (const float*)d_in[14];
    float* out = (float*)d_out;

    const int dwSmem  = 3168 * 16;
    const int offSmem = 3168 * 16 + 5184 * 4;
    static int configured = 0;
    if (!configured) {
        cudaFuncSetAttribute(k_dw,  cudaFuncAttributeMaxDynamicSharedMemorySize, dwSmem);
        cudaFuncSetAttribute(k_off, cudaFuncAttributeMaxDynamicSharedMemorySize, offSmem);
        configured = 1;
    }

    k_ln<<<PP / 32, 256>>>(x, ln1_g, ln1_b);
    k_gemm<0><<<dim3(3, PP / 128), 256>>>(w_qkv, nullptr, nullptr, nullptr);
    k_dw<<<16 * 16, 256, dwSmem>>>(w_dw, ln2_g, ln2_b);
    k_off<<<16 * 16, 256, offSmem>>>(w_off, b_off, offset);
    k_attn<<<(PP * 4) / 128, 128>>>(rpb);
    k_gemm<1><<<dim3(4, PP / 128), 256>>>(w_proj, b_proj, x, nullptr);
    k_gemm<2><<<dim3(2, PP / 128), 256>>>(w_cls, b_cls, nullptr, out);
}

// round 7
// speedup vs baseline: 1.7828x; 1.0696x over previous
#include <cuda_runtime.h>
#include <cuda_bf16.h>
#include <cuda_fp16.h>
#include <math.h>

// ---------------- static config ----------------
#define HWP   4096
#define PP    32768
#define DIMC  256
#define CRC   64
#define GCC   32
#define HCC   16
#define N9    9
#define OFFC  18
#define NCLS  80
#define SCALEF 0.25f
#define MULF  5.0f

// ---------------- scratch ----------------
__device__ float  g_xn[PP * DIMC];
__device__ float  g_qbuf[PP * CRC];
__device__ __half g_kbufh[16 * HWP * GCC];
__device__ __half g_vbufh[16 * HWP * GCC];
__device__ float  g_tbuf[16 * HWP * GCC];
__device__ float  g_offbuf[16 * HWP * OFFC];
__device__ float  g_attnout[PP * CRC];
__device__ float  g_ybuf[PP * DIMC];

// ---------------- kernel 1: channel-LN + NCHW -> [P,C] transpose ----------------
__global__ void k_ln(const float* __restrict__ x,
                     const float* __restrict__ gam,
                     const float* __restrict__ bet)
{
    __shared__ float s[DIMC][33];
    __shared__ float red[2][8][32];
    __shared__ float smean[32], srstd[32];

    int p0 = blockIdx.x * 32;
    int b  = p0 >> 12;
    int hw0 = p0 & 4095;
    int tid = threadIdx.x;
    int tx = tid & 31, ty = tid >> 5;

    const float* xb = x + (size_t)b * DIMC * HWP + hw0;
    for (int c = ty; c < DIMC; c += 8)
        s[c][tx] = xb[c * HWP + tx];
    __syncthreads();

    float sum = 0.f, sq = 0.f;
    for (int c = ty; c < DIMC; c += 8) {
        float v = s[c][tx];
        sum += v; sq += v * v;
    }
    red[0][ty][tx] = sum; red[1][ty][tx] = sq;
    __syncthreads();
    if (ty == 0) {
        float s1 = 0.f, s2 = 0.f;
        #pragma unroll
        for (int j = 0; j < 8; j++) { s1 += red[0][j][tx]; s2 += red[1][j][tx]; }
        float m = s1 * (1.f / 256.f);
        float v = s2 * (1.f / 256.f) - m * m;
        smean[tx] = m;
        srstd[tx] = rsqrtf(v + 1e-5f);
    }
    __syncthreads();

    float gg = gam[tid], bb = bet[tid];
    for (int pl = 0; pl < 32; pl++) {
        g_xn[(size_t)(p0 + pl) * DIMC + tid] =
            (s[tid][pl] - smean[pl]) * srstd[pl] * gg + bb;
    }
}

// ---------------- helpers: bf16 split + mma ----------------
__device__ __forceinline__ void cvt_pair(float x0, float x1,
                                         unsigned& hi, unsigned& lo)
{
    __nv_bfloat16 h0 = __float2bfloat16(x0);
    __nv_bfloat16 h1 = __float2bfloat16(x1);
    float r0 = x0 - __bfloat162float(h0);
    float r1 = x1 - __bfloat162float(h1);
    __nv_bfloat16 l0 = __float2bfloat16(r0);
    __nv_bfloat16 l1 = __float2bfloat16(r1);
    unsigned short u0 = *(unsigned short*)&h0, u1 = *(unsigned short*)&h1;
    unsigned short v0 = *(unsigned short*)&l0, v1 = *(unsigned short*)&l1;
    hi = (unsigned)u0 | ((unsigned)u1 << 16);
    lo = (unsigned)v0 | ((unsigned)v1 << 16);
}

__device__ __forceinline__ void mma_bf16(float* c,
                                         unsigned a0, unsigned a1, unsigned a2, unsigned a3,
                                         unsigned b0, unsigned b1)
{
    asm volatile(
        "mma.sync.aligned.m16n8k16.row.col.f32.bf16.bf16.f32 "
        "{%0,%1,%2,%3}, {%4,%5,%6,%7}, {%8,%9}, {%0,%1,%2,%3};\n"
        : "+f"(c[0]), "+f"(c[1]), "+f"(c[2]), "+f"(c[3])
        : "r"(a0), "r"(a1), "r"(a2), "r"(a3), "r"(b0), "r"(b1));
}

// ---------------- tensor-core GEMM (bf16 split, 3xMMA) with reg prefetch -------
template<int MODE>
__global__ void __launch_bounds__(256) k_gemm(const float* __restrict__ Bw,
                                              const float* __restrict__ bias,
                                              const float* __restrict__ resid,
                                              float* __restrict__ outp)
{
    constexpr int K    = (MODE == 1) ? 64 : 256;
    constexpr int Ntot = (MODE == 0) ? 192 : (MODE == 1) ? 256 : 80;
    const float* A = (MODE == 0) ? g_xn : (MODE == 1) ? g_attnout : g_ybuf;

    __shared__ unsigned Ah[128][20], Al[128][20];
    __shared__ unsigned Bh[64][20],  Bl[64][20];

    int tid = threadIdx.x;
    int lane = tid & 31;
    int warpId = tid >> 5;
    int warpM = warpId & 3;
    int warpN = warpId >> 2;
    int row0 = blockIdx.y * 128, col0 = blockIdx.x * 64;

    float acc[2][4][4];
    #pragma unroll
    for (int mt = 0; mt < 2; mt++)
        #pragma unroll
        for (int nt = 0; nt < 4; nt++)
            #pragma unroll
            for (int e = 0; e < 4; e++) acc[mt][nt][e] = 0.f;

    // prefetch registers
    float4 pa[4], pb[2];

    // load chunk k0=0
    #pragma unroll
    for (int i = 0; i < 4; i++) {
        int id = tid + i * 256;
        int row = id >> 3, f = id & 7;
        pa[i] = *(const float4*)(A + (size_t)(row0 + row) * K + 0 + f * 4);
    }
    #pragma unroll
    for (int i = 0; i < 2; i++) {
        int id = tid + i * 256;
        int row = id >> 3, f = id & 7;
        pb[i] = make_float4(0.f, 0.f, 0.f, 0.f);
        if (col0 + row < Ntot)
            pb[i] = *(const float4*)(Bw + (size_t)(col0 + row) * K + 0 + f * 4);
    }

    for (int k0 = 0; k0 < K; k0 += 32) {
        // store prefetched chunk to smem (with split conversion)
        #pragma unroll
        for (int i = 0; i < 4; i++) {
            int id = tid + i * 256;
            int row = id >> 3, f = id & 7;
            unsigned h0, l0, h1, l1;
            cvt_pair(pa[i].x, pa[i].y, h0, l0);
            cvt_pair(pa[i].z, pa[i].w, h1, l1);
            Ah[row][f * 2] = h0; Ah[row][f * 2 + 1] = h1;
            Al[row][f * 2] = l0; Al[row][f * 2 + 1] = l1;
        }
        #pragma unroll
        for (int i = 0; i < 2; i++) {
            int id = tid + i * 256;
            int row = id >> 3, f = id & 7;
            unsigned h0, l0, h1, l1;
            cvt_pair(pb[i].x, pb[i].y, h0, l0);
            cvt_pair(pb[i].z, pb[i].w, h1, l1);
            Bh[row][f * 2] = h0; Bh[row][f * 2 + 1] = h1;
            Bl[row][f * 2] = l0; Bl[row][f * 2 + 1] = l1;
        }
        __syncthreads();

        // issue prefetch for next chunk (overlaps with MMA below)
        if (k0 + 32 < K) {
            #pragma unroll
            for (int i = 0; i < 4; i++) {
                int id = tid + i * 256;
                int row = id >> 3, f = id & 7;
                pa[i] = *(const float4*)(A + (size_t)(row0 + row) * K + (k0 + 32) + f * 4);
            }
            #pragma unroll
            for (int i = 0; i < 2; i++) {
                int id = tid + i * 256;
                int row = id >> 3, f = id & 7;
                pb[i] = make_float4(0.f, 0.f, 0.f, 0.f);
                if (col0 + row < Ntot)
                    pb[i] = *(const float4*)(Bw + (size_t)(col0 + row) * K + (k0 + 32) + f * 4);
            }
        }

        #pragma unroll
        for (int kk = 0; kk < 2; kk++) {
            int kb = kk * 8 + (lane & 3);
            unsigned ah[2][4], al[2][4];
            #pragma unroll
            for (int mt = 0; mt < 2; mt++) {
                int ar = warpM * 32 + mt * 16 + (lane >> 2);
                ah[mt][0] = Ah[ar][kb];     ah[mt][1] = Ah[ar + 8][kb];
                ah[mt][2] = Ah[ar][kb + 4]; ah[mt][3] = Ah[ar + 8][kb + 4];
                al[mt][0] = Al[ar][kb];     al[mt][1] = Al[ar + 8][kb];
                al[mt][2] = Al[ar][kb + 4]; al[mt][3] = Al[ar + 8][kb + 4];
            }
            #pragma unroll
            for (int nt = 0; nt < 4; nt++) {
                int br = warpN * 32 + nt * 8 + (lane >> 2);
                unsigned bh0 = Bh[br][kb], bh1 = Bh[br][kb + 4];
                unsigned bl0 = Bl[br][kb], bl1 = Bl[br][kb + 4];
                #pragma unroll
                for (int mt = 0; mt < 2; mt++) {
                    mma_bf16(acc[mt][nt], ah[mt][0], ah[mt][1], ah[mt][2], ah[mt][3], bh0, bh1);
                    mma_bf16(acc[mt][nt], ah[mt][0], ah[mt][1], ah[mt][2], ah[mt][3], bl0, bl1);
                    mma_bf16(acc[mt][nt], al[mt][0], al[mt][1], al[mt][2], al[mt][3], bh0, bh1);
                }
            }
        }
        __syncthreads();
    }

    #pragma unroll
    for (int mt = 0; mt < 2; mt++) {
        #pragma unroll
        for (int nt = 0; nt < 4; nt++) {
            #pragma unroll
            for (int e = 0; e < 4; e++) {
                int p = row0 + warpM * 32 + mt * 16 + (lane >> 2) + ((e >= 2) ? 8 : 0);
                int o = col0 + warpN * 32 + nt * 8 + 2 * (lane & 3) + (e & 1);
                float v = acc[mt][nt][e];
                int bidx = p >> 12, hw = p & 4095;
                if (MODE == 0) {
                    if (o < 64) {
                        g_qbuf[p * 64 + o] = v;
                    } else if (o < 128) {
                        int c = o - 64;
                        g_kbufh[((size_t)(bidx * 2 + (c >> 5)) * HWP + hw) * GCC + (c & 31)] =
                            __float2half(v);
                    } else {
                        int c = o - 128;
                        g_vbufh[((size_t)(bidx * 2 + (c >> 5)) * HWP + hw) * GCC + (c & 31)] =
                            __float2half(v);
                    }
                } else if (MODE == 1) {
                    g_ybuf[(size_t)p * DIMC + o] =
                        v + bias[o] + resid[(size_t)bidx * DIMC * HWP + o * HWP + hw];
                } else {
                    if (o < Ntot)
                        outp[(size_t)bidx * NCLS * HWP + o * HWP + hw] = v + bias[o];
                }
            }
        }
    }
}

// ---------------- kernel 3: smem-tiled depthwise 3x3 + LN(32) + GELU ----------
__global__ void __launch_bounds__(256, 2) k_dw(const float* __restrict__ wdw,
                                               const float* __restrict__ g2,
                                               const float* __restrict__ b2)
{
    extern __shared__ float4 st4[];
    __shared__ float sw[GCC * 9];
    __shared__ float sg[GCC], sb[GCC];

    int bg = blockIdx.x >> 4;
    int h0 = (blockIdx.x & 15) * 4;
    int b = bg >> 1, g = bg & 1;
    int tid = threadIdx.x;

    for (int i = tid; i < GCC * 9; i += 256) sw[i] = wdw[i];
    if (tid < GCC) { sg[tid] = g2[tid]; sb[tid] = b2[tid]; }
    for (int i = tid; i < 3168; i += 256) st4[i] = make_float4(0.f, 0.f, 0.f, 0.f);
    __syncthreads();

    for (int i = tid; i < 3072; i += 256) {
        int c4 = i & 7, col = (i >> 3) & 63, r = i >> 9;
        int gr = h0 - 1 + r;
        if ((unsigned)gr < 64u)
            st4[(c4 * 6 + r) * 66 + col + 1] =
                *(const float4*)(g_qbuf + ((size_t)(b * HWP + gr * 64 + col)) * CRC + g * GCC + c4 * 4);
    }
    __syncthreads();

    int col = tid & 63;
    int row = tid >> 6;
    int h = h0 + row;

    float acc[GCC];
    #pragma unroll
    for (int c = 0; c < GCC; c++) acc[c] = 0.f;

    #pragma unroll
    for (int ky = 0; ky < 3; ky++) {
        #pragma unroll
        for (int kx = 0; kx < 3; kx++) {
            int kidx = ky * 3 + kx;
            #pragma unroll
            for (int c4 = 0; c4 < 8; c4++) {
                float4 v = st4[(c4 * 6 + row + ky) * 66 + col + kx];
                acc[c4 * 4 + 0] += v.x * sw[(c4 * 4 + 0) * 9 + kidx];
                acc[c4 * 4 + 1] += v.y * sw[(c4 * 4 + 1) * 9 + kidx];
                acc[c4 * 4 + 2] += v.z * sw[(c4 * 4 + 2) * 9 + kidx];
                acc[c4 * 4 + 3] += v.w * sw[(c4 * 4 + 3) * 9 + kidx];
            }
        }
    }

    float m = 0.f;
    #pragma unroll
    for (int c = 0; c < GCC; c++) m += acc[c];
    m *= (1.f / GCC);
    float v = 0.f;
    #pragma unroll
    for (int c = 0; c < GCC; c++) { float d = acc[c] - m; v += d * d; }
    float rs = rsqrtf(v * (1.f / GCC) + 1e-5f);

    float* dst = g_tbuf + ((size_t)bg * HWP + h * 64 + col) * GCC;
    #pragma unroll
    for (int c = 0; c < GCC; c++) {
        float t = (acc[c] - m) * rs * sg[c] + sb[c];
        dst[c] = 0.5f * t * (1.f + erff(t * 0.70710678118654752f));
    }
}

// ---------------- kernel 4: smem-tiled 3x3 conv (32->18), 2 rows/block --------
// Block = (bg, 2 rows). 256 threads = 64 cols x 2 og x 2 rows, 1 px/thread.
__global__ void __launch_bounds__(256) k_off(const float* __restrict__ woff,
                                             const float* __restrict__ boff,
                                             const float* __restrict__ offset)
{
    extern __shared__ float4 dyn4[];
    float4* st4 = dyn4;                       // 8 c4 * 4 rows * 66 = 2112 float4
    float*  sw  = (float*)(dyn4 + 2112);      // [9][18][32]
    float4* sw4 = (float4*)sw;

    int bg = blockIdx.x >> 5;
    int h0 = (blockIdx.x & 31) * 2;
    int tid = threadIdx.x;

    for (int i = tid; i < OFFC * GCC * 9; i += 256) {
        int o = i / (GCC * 9); int rem = i - o * (GCC * 9);
        int c = rem / 9; int kidx = rem - c * 9;
        sw[(kidx * OFFC + o) * GCC + c] = woff[i];
    }
    for (int i = tid; i < 2112; i += 256) st4[i] = make_float4(0.f, 0.f, 0.f, 0.f);
    __syncthreads();

    // stage rows h0-1 .. h0+2
    for (int i = tid; i < 2048; i += 256) {
        int c4 = i & 7, col = (i >> 3) & 63, r = i >> 9;
        int gr = h0 - 1 + r;
        if ((unsigned)gr < 64u)
            st4[(c4 * 4 + r) * 66 + col + 1] =
                *(const float4*)(g_tbuf + ((size_t)(bg * HWP + gr * 64 + col)) * GCC + c4 * 4);
    }
    __syncthreads();

    int col = tid & 63;
    int og  = (tid >> 6) & 1;
    int row = tid >> 7;
    int h = h0 + row;
    int b = bg >> 1;

    float acc[9];
    #pragma unroll
    for (int o = 0; o < 9; o++) acc[o] = boff[og * 9 + o];

    #pragma unroll
    for (int c4 = 0; c4 < 8; c4++) {
        #pragma unroll
        for (int ky = 0; ky < 3; ky++) {
            const float4* trow = &st4[(c4 * 4 + row + ky) * 66];
            float4 t[3];
            t[0] = trow[col]; t[1] = trow[col + 1]; t[2] = trow[col + 2];
            #pragma unroll
            for (int kx = 0; kx < 3; kx++) {
                int kidx = ky * 3 + kx;
                #pragma unroll
                for (int o = 0; o < 9; o++) {
                    float4 w = sw4[(kidx * OFFC + og * 9 + o) * 8 + c4];
                    acc[o] += t[kx].x * w.x + t[kx].y * w.y +
                              t[kx].z * w.z + t[kx].w * w.w;
                }
            }
        }
    }

    int hw = h * 64 + col;
    const float* ofs = offset + (size_t)b * OFFC * HWP + hw;
    float* dst = g_offbuf + ((size_t)bg * HWP + hw) * OFFC + og * 9;
    #pragma unroll
    for (int o = 0; o < 9; o++)
        dst[o] = tanhf(acc[o]) * MULF + ofs[(og * 9 + o) * HWP];
}

// ---------------- kernel 5: deformable gather + softmax attention (fp16 k/v) ---
__device__ __forceinline__ void samp16h(const __half* __restrict__ bufh,
                                        int y, int x, float w, float s[16])
{
    if ((unsigned)x < 64u && (unsigned)y < 64u) {
        const uint4* q = (const uint4*)(bufh + (y * 64 + x) * GCC);
        uint4 u0 = q[0], u1 = q[1];
        const __half2* h0 = (const __half2*)&u0;
        const __half2* h1 = (const __half2*)&u1;
        #pragma unroll
        for (int i = 0; i < 4; i++) {
            float2 f = __half22float2(h0[i]);
            s[2 * i]     += w * f.x;
            s[2 * i + 1] += w * f.y;
        }
        #pragma unroll
        for (int i = 0; i < 4; i++) {
            float2 f = __half22float2(h1[i]);
            s[8 + 2 * i]     += w * f.x;
            s[8 + 2 * i + 1] += w * f.y;
        }
    }
}

__global__ void k_attn(const float* __restrict__ rpb)
{
    int idx = blockIdx.x * blockDim.x + threadIdx.x;
    int nh = idx & 3;
    int p  = idx >> 2;
    int b = p >> 12, hw = p & 4095;
    int g = nh >> 1, hb = (nh & 1) * 16;
    int bg = b * 2 + g;

    float q[16];
    const float* qp = g_qbuf + (size_t)p * CRC + nh * HCC;
    #pragma unroll
    for (int i = 0; i < 16; i++) q[i] = qp[i] * SCALEF;

    const float* off = g_offbuf + (size_t)(bg * HWP + hw) * OFFC;
    const __half* kb = g_kbufh + (size_t)bg * HWP * GCC + hb;
    const __half* vb = g_vbufh + (size_t)bg * HWP * GCC + hb;
    const float* rp = rpb + nh * (N9 * HCC);

    int ix[N9], iy[N9];
    float fx[N9], fy[N9], logit[N9];

    #pragma unroll
    for (int n = 0; n < N9; n++) {
        float row = off[2 * n], col = off[2 * n + 1];
        float xf = floorf(col), yf = floorf(row);
        ix[n] = (int)xf; iy[n] = (int)yf;
        fx[n] = col - xf; fy[n] = row - yf;

        float w00 = (1.f - fx[n]) * (1.f - fy[n]);
        float w10 = fx[n] * (1.f - fy[n]);
        float w01 = (1.f - fx[n]) * fy[n];
        float w11 = fx[n] * fy[n];

        float s[16];
        #pragma unroll
        for (int i = 0; i < 16; i++) s[i] = 0.f;
        samp16h(kb, iy[n],     ix[n],     w00, s);
        samp16h(kb, iy[n],     ix[n] + 1, w10, s);
        samp16h(kb, iy[n] + 1, ix[n],     w01, s);
        samp16h(kb, iy[n] + 1, ix[n] + 1, w11, s);

        float l = 0.f;
        const float* rpn = rp + n * HCC;
        #pragma unroll
        for (int i = 0; i < 16; i++) l += q[i] * (s[i] + rpn[i]);
        logit[n] = l;
    }

    float mx = logit[0];
    #pragma unroll
    for (int n = 1; n < N9; n++) mx = fmaxf(mx, logit[n]);
    float sum = 0.f;
    #pragma unroll
    for (int n = 0; n < N9; n++) { logit[n] = expf(logit[n] - mx); sum += logit[n]; }
    float inv = 1.f / sum;

    float o16[16];
    #pragma unroll
    for (int i = 0; i < 16; i++) o16[i] = 0.f;

    #pragma unroll
    for (int n = 0; n < N9; n++) {
        float wn = logit[n] * inv;
        float w00 = (1.f - fx[n]) * (1.f - fy[n]) * wn;
        float w10 = fx[n] * (1.f - fy[n]) * wn;
        float w01 = (1.f - fx[n]) * fy[n] * wn;
        float w11 = fx[n] * fy[n] * wn;
        samp16h(vb, iy[n],     ix[n],     w00, o16);
        samp16h(vb, iy[n],     ix[n] + 1, w10, o16);
        samp16h(vb, iy[n] + 1, ix[n],     w01, o16);
        samp16h(vb, iy[n] + 1, ix[n] + 1, w11, o16);
    }

    float* dst = g_attnout + (size_t)p * CRC + nh * HCC;
    #pragma unroll
    for (int i = 0; i < 16; i++) dst[i] = o16[i];
}

// ---------------- launch ----------------
extern "C" void kernel_launch(void* const* d_in, const int* in_sizes, int n_in,
                              void* d_out, int out_size)
{
    const float* x      = (const float*)d_in[0];
    const float* offset = (const float*)d_in[1];
    const float* ln1_g  = (const float*)d_in[2];
    const float* ln1_b  = (const float*)d_in[3];
    const float* w_qkv  = (const float*)d_in[4];
    const float* w_dw   = (const float*)d_in[5];
    const float* ln2_g  = (const float*)d_in[6];
    const float* ln2_b  = (const float*)d_in[7];
    const float* w_off  = (const float*)d_in[8];
    const float* b_off  = (const float*)d_in[9];
    const float* rpb    = (const float*)d_in[10];
    const float* w_proj = (const float*)d_in[11];
    const float* b_proj = (const float*)d_in[12];
    const float* w_cls  = (const float*)d_in[13];
    const float* b_cls  = (const float*)d_in[14];
    float* out = (float*)d_out;

    const int dwSmem  = 3168 * 16;                    // 50688 B
    const int offSmem = 2112 * 16 + 5184 * 4;         // 54528 B
    static int configured = 0;
    if (!configured) {
        cudaFuncSetAttribute(k_dw,  cudaFuncAttributeMaxDynamicSharedMemorySize, dwSmem);
        cudaFuncSetAttribute(k_off, cudaFuncAttributeMaxDynamicSharedMemorySize, offSmem);
        configured = 1;
    }

    k_ln<<<PP / 32, 256>>>(x, ln1_g, ln1_b);
    k_gemm<0><<<dim3(3, PP / 128), 256>>>(w_qkv, nullptr, nullptr, nullptr);
    k_dw<<<16 * 16, 256, dwSmem>>>(w_dw, ln2_g, ln2_b);
    k_off<<<16 * 32, 256, offSmem>>>(w_off, b_off, offset);
    k_attn<<<(PP * 4) / 128, 128>>>(rpb);
    k_gemm<1><<<dim3(4, PP / 128), 256>>>(w_proj, b_proj, x, nullptr);
    k_gemm<2><<<dim3(2, PP / 128), 256>>>(w_cls, b_cls, nullptr, out);
}